// round 10
// baseline (speedup 1.0000x reference)
#include <cuda_runtime.h>
#include <cuda_bf16.h>
#include <cstdint>

// ---------------- fixed shapes ----------------
#define NS      51
#define T_LEN   2048
#define B_TOT   8192
#define M_ROWS  64
#define NCTA    (B_TOT / M_ROWS)      // 128
#define NTHREADS 512                  // 16 warps = 4 m-groups x 4 n-groups
#define MAXT    7                     // max n-tiles per warp

// SMEM tiles
#define APITCH  528                   // A: [64 rows][256 bf16]  (h1hi|h1lo|h2hi|h2lo)
#define B1P     272                   // B1: [208 n][128 bf16]   (W1hi|W1lo)
#define B2P     528                   // B2: [208 n][256 bf16]   (Wi2hi|Wi2lo|Wh2hi|Wh2lo)

#define OFF_A   0
#define A_BYTES (64 * APITCH)                 // 33792
#define OFF_B1  (OFF_A + A_BYTES)
#define B1_BYTES (208 * B1P)                  // 56576
#define OFF_B2  (OFF_B1 + B1_BYTES)
#define B2_BYTES (208 * B2P)                  // 109824
#define OFF_B1Q (OFF_B2 + B2_BYTES)           // float4[52]
#define OFF_B2Q (OFF_B1Q + 832)
#define OFF_WXQ (OFF_B2Q + 832)
#define OFF_WLS (OFF_WXQ + 832)               // float[52] (+pad)
#define OFF_YW  (OFF_WLS + 224)               // float[64][8]
#define SMEM_TOTAL (OFF_YW + 64 * 8 * 4)      // 204960

typedef uint32_t u32;

// ---------------- helpers ----------------
__device__ __forceinline__ u32 smem_u32(const void* p) {
    u32 a;
    asm("{ .reg .u64 t; cvta.to.shared.u64 t, %1; cvt.u32.u64 %0, t; }" : "=r"(a) : "l"(p));
    return a;
}
__device__ __forceinline__ void ldsm4(u32* r, u32 addr) {
    asm volatile("ldmatrix.sync.aligned.m8n8.x4.shared.b16 {%0,%1,%2,%3}, [%4];"
                 : "=r"(r[0]), "=r"(r[1]), "=r"(r[2]), "=r"(r[3]) : "r"(addr));
}
__device__ __forceinline__ void mma_bf16(float* c, const u32* a, const u32* b) {
    asm volatile("mma.sync.aligned.m16n8k16.row.col.f32.bf16.bf16.f32 "
                 "{%0,%1,%2,%3}, {%4,%5,%6,%7}, {%8,%9}, {%0,%1,%2,%3};"
                 : "+f"(c[0]), "+f"(c[1]), "+f"(c[2]), "+f"(c[3])
                 : "r"(a[0]), "r"(a[1]), "r"(a[2]), "r"(a[3]), "r"(b[0]), "r"(b[1]));
}
__device__ __forceinline__ float sigm(float v) { return 1.0f / (1.0f + __expf(-v)); }
__device__ __forceinline__ float tanh_fast(float v) { return 2.0f / (1.0f + __expf(-2.0f * v)) - 1.0f; }

// A-fragment (m16k16): m0 = absolute first row of this warp's 16-row tile
__device__ __forceinline__ u32 a_addr(u32 sbA, int m0, int kchunk, int lane) {
    int r  = m0 + (lane & 15);
    int cb = kchunk * 32 + ((lane >> 4) << 4);
    return sbA + r * APITCH + cb;
}
// B-fragment x4 (one n8 tile, two k16 tiles starting at kchunk)
__device__ __forceinline__ u32 b_addr(u32 sbB, int pitch, int nt, int kchunk, int lane) {
    int n  = nt * 8 + (lane & 7);
    int cb = kchunk * 32 + ((lane >> 3) << 4);
    return sbB + n * pitch + cb;
}

// Regroup D-frag gates: after this each lane owns (i,f,g,o) of ONE (row,unit).
// even lane: row = lane>>2 (within tile); odd lane: row = (lane>>2)+8.
__device__ __forceinline__ void regroup(const float* C, int lane,
                                        float& gi_, float& gf, float& gg, float& go) {
    float v  = (lane & 1) ? C[0] : C[2];
    float sv = __shfl_xor_sync(0xFFFFFFFFu, v, 1);
    float w  = (lane & 1) ? C[1] : C[3];
    float sw = __shfl_xor_sync(0xFFFFFFFFu, w, 1);
    if (lane & 1) { gi_ = sv;   gf = sw;   gg = C[2]; go = C[3]; }
    else          { gi_ = C[0]; gf = C[1]; gg = sv;   go = sw;  }
}

__device__ __forceinline__ void store_h(char* smem, int row, int colbase, float h) {
    __nv_bfloat16 hh = __float2bfloat16(h);
    __nv_bfloat16 hl = __float2bfloat16(h - __bfloat162float(hh));
    *(__nv_bfloat16*)(smem + OFF_A + row * APITCH + colbase * 2)        = hh;
    *(__nv_bfloat16*)(smem + OFF_A + row * APITCH + (colbase + 64) * 2) = hl;
}

// Layer-1 epilogue (single row per lane)
__device__ __forceinline__ void epi_l1(
    float acc[MAXT][4], int cnt, int nt0, int lane, int jpar, int row,
    const float4* b1q, const float4* wxq, float xv, float* c1, char* smem)
{
    #pragma unroll
    for (int nti = 0; nti < MAXT; ++nti) if (nti < cnt) {
        float gi_, gf, gg, go;
        regroup(acc[nti], lane, gi_, gf, gg, go);
        int j = 2 * (nt0 + nti) + jpar;
        float4 b  = b1q[j];
        float4 wx = wxq[j];
        float pi = fmaf(xv, wx.x, gi_ + b.x);
        float pf = fmaf(xv, wx.y, gf + b.y);
        float pg = fmaf(xv, wx.z, gg + b.z);
        float po = fmaf(xv, wx.w, go + b.w);
        float cn = fmaf(sigm(pf), c1[nti], sigm(pi) * tanh_fast(pg));
        c1[nti] = cn;
        float h = sigm(po) * tanh_fast(cn);
        if (j < NS) store_h(smem, row, j, h);
    }
}

// Layer-2 epilogue (+ y partials)
__device__ __forceinline__ void epi_l2(
    float acc[MAXT][4], int cnt, int nt0, int lane, int jpar, int row,
    const float4* b2q, const float* wls, float* c2, char* smem, float* yw, int ng)
{
    float yp = 0.0f;
    #pragma unroll
    for (int nti = 0; nti < MAXT; ++nti) if (nti < cnt) {
        float gi_, gf, gg, go;
        regroup(acc[nti], lane, gi_, gf, gg, go);
        int j = 2 * (nt0 + nti) + jpar;
        float4 b = b2q[j];
        float pi = gi_ + b.x, pf = gf + b.y, pg = gg + b.z, po = go + b.w;
        float cn = fmaf(sigm(pf), c2[nti], sigm(pi) * tanh_fast(pg));
        c2[nti] = cn;
        float h = sigm(po) * tanh_fast(cn);
        if (j < NS) {
            store_h(smem, row, 128 + j, h);
            yp = fmaf(wls[j], h, yp);
        }
    }
    float ys = yp + __shfl_xor_sync(0xFFFFFFFFu, yp, 2);   // combine jpar pair
    if (!(lane & 2)) yw[row * 8 + ng] = ys;
}

__global__ __launch_bounds__(NTHREADS, 1)
void lstm2_hmma16_kernel(
    const float* __restrict__ x,      // [B, T]
    const float* __restrict__ Wih1,   // [204, 1]
    const float* __restrict__ Whh1,   // [204, 51]
    const float* __restrict__ bih1,
    const float* __restrict__ bhh1,
    const float* __restrict__ Wih2,   // [204, 51]
    const float* __restrict__ Whh2,   // [204, 51]
    const float* __restrict__ bih2,
    const float* __restrict__ bhh2,
    const float* __restrict__ Wlin,   // [1, 51]
    const float* __restrict__ blin,
    float* __restrict__ out)          // [B, T]
{
    extern __shared__ char smem[];
    const u32 sb = smem_u32(smem);
    const int tid  = threadIdx.x;
    const int wid  = tid >> 5;
    const int lane = tid & 31;
    const int mg   = wid >> 2;                // m-group 0..3 (16 rows each)
    const int ng   = wid & 3;                 // n-group 0..3
    const int cnt  = (ng < 2) ? 7 : 6;        // n-tiles owned (7+7+6+6 = 26)
    const int nt0  = (ng < 2) ? 7 * ng : 14 + 6 * (ng - 2);
    const int rb   = blockIdx.x * M_ROWS;

    for (int i = tid; i < SMEM_TOTAL / 4; i += NTHREADS) ((u32*)smem)[i] = 0;
    __syncthreads();

    float4* b1q = (float4*)(smem + OFF_B1Q);
    float4* b2q = (float4*)(smem + OFF_B2Q);
    float4* wxq = (float4*)(smem + OFF_WXQ);
    float*  wls = (float*)(smem + OFF_WLS);
    float*  yw  = (float*)(smem + OFF_YW);

    // ---- weights: B row n = 4*j + gi, hi/lo bf16 split ----
    for (int idx = tid; idx < 208 * NS; idx += NTHREADS) {
        int n = idx / NS, m = idx % NS;
        int j = n >> 2, gi = n & 3;
        if (j < NS) {
            int g = gi * NS + j;
            float w1  = Whh1[g * NS + m];
            float wi2 = Wih2[g * NS + m];
            float wh2 = Whh2[g * NS + m];
            __nv_bfloat16 h, l;
            h = __float2bfloat16(w1);  l = __float2bfloat16(w1 - __bfloat162float(h));
            *(__nv_bfloat16*)(smem + OFF_B1 + n * B1P + m * 2)        = h;
            *(__nv_bfloat16*)(smem + OFF_B1 + n * B1P + (64 + m) * 2) = l;
            h = __float2bfloat16(wi2); l = __float2bfloat16(wi2 - __bfloat162float(h));
            *(__nv_bfloat16*)(smem + OFF_B2 + n * B2P + m * 2)        = h;
            *(__nv_bfloat16*)(smem + OFF_B2 + n * B2P + (64 + m) * 2) = l;
            h = __float2bfloat16(wh2); l = __float2bfloat16(wh2 - __bfloat162float(h));
            *(__nv_bfloat16*)(smem + OFF_B2 + n * B2P + (128 + m) * 2) = h;
            *(__nv_bfloat16*)(smem + OFF_B2 + n * B2P + (192 + m) * 2) = l;
        }
    }
    for (int j = tid; j < NS; j += NTHREADS) {
        b1q[j] = make_float4(bih1[j] + bhh1[j], bih1[j + NS] + bhh1[j + NS],
                             bih1[j + 2 * NS] + bhh1[j + 2 * NS], bih1[j + 3 * NS] + bhh1[j + 3 * NS]);
        b2q[j] = make_float4(bih2[j] + bhh2[j], bih2[j + NS] + bhh2[j + NS],
                             bih2[j + 2 * NS] + bhh2[j + 2 * NS], bih2[j + 3 * NS] + bhh2[j + 3 * NS]);
        wxq[j] = make_float4(Wih1[j], Wih1[j + NS], Wih1[j + 2 * NS], Wih1[j + 3 * NS]);
        wls[j] = Wlin[j];
    }
    __syncthreads();

    const float blin_v = blin[0];
    const int m0   = 16 * mg;                               // warp's A-row base
    const int row  = m0 + (lane >> 2) + 8 * (lane & 1);     // this lane's row
    const int jpar = (lane >> 1) & 1;
    const u32 sbA  = sb + OFF_A;
    const u32 sbB1 = sb + OFF_B1;
    const u32 sbB2 = sb + OFF_B2;

    float c1[MAXT], c2[MAXT];
    #pragma unroll
    for (int i = 0; i < MAXT; ++i) { c1[i] = 0.0f; c2[i] = 0.0f; }

    // ---- prologue: h1(0) = L1(x(0), h=0, c=0) ----
    {
        float acc0[MAXT][4];
        #pragma unroll
        for (int i = 0; i < MAXT; ++i)
            #pragma unroll
            for (int q = 0; q < 4; ++q) acc0[i][q] = 0.0f;
        float xv0 = __ldg(&x[(size_t)(rb + row) * T_LEN]);
        epi_l1(acc0, cnt, nt0, lane, jpar, row, b1q, wxq, xv0, c1, smem);
    }
    __syncthreads();

    // ---- main loop: step t uses tile {h1(t), h2(t-1)} ----
    for (int t = 0; t < T_LEN; ++t) {
        float xv = (t + 1 < T_LEN)
                 ? __ldg(&x[(size_t)(rb + row) * T_LEN + t + 1]) : 0.0f;

        float acc1[MAXT][4], acc2[MAXT][4];
        #pragma unroll
        for (int i = 0; i < MAXT; ++i)
            #pragma unroll
            for (int q = 0; q < 4; ++q) { acc1[i][q] = 0.0f; acc2[i][q] = 0.0f; }

        // ---- P12: acc1 += h1*W1 ; acc2 += h1*Wi2  (shared h1 A-frags) ----
        #pragma unroll
        for (int half = 0; half < 2; ++half) {
            u32 ahi[2][4], alo[2][4];
            #pragma unroll
            for (int kk = 0; kk < 2; ++kk) {
                ldsm4(ahi[kk], a_addr(sbA, m0, 2 * half + kk, lane));
                ldsm4(alo[kk], a_addr(sbA, m0, 4 + 2 * half + kk, lane));
            }
            #pragma unroll
            for (int nti = 0; nti < MAXT; ++nti) if (nti < cnt) {
                int nt = nt0 + nti;
                u32 bh[4], bl[4];
                ldsm4(bh, b_addr(sbB1, B1P, nt, 2 * half, lane));
                ldsm4(bl, b_addr(sbB1, B1P, nt, 4 + 2 * half, lane));
                #pragma unroll
                for (int kk = 0; kk < 2; ++kk) {
                    mma_bf16(acc1[nti], ahi[kk], bh + 2 * kk);
                    mma_bf16(acc1[nti], alo[kk], bh + 2 * kk);
                    mma_bf16(acc1[nti], ahi[kk], bl + 2 * kk);
                }
                ldsm4(bh, b_addr(sbB2, B2P, nt, 2 * half, lane));
                ldsm4(bl, b_addr(sbB2, B2P, nt, 4 + 2 * half, lane));
                #pragma unroll
                for (int kk = 0; kk < 2; ++kk) {
                    mma_bf16(acc2[nti], ahi[kk], bh + 2 * kk);
                    mma_bf16(acc2[nti], alo[kk], bh + 2 * kk);
                    mma_bf16(acc2[nti], ahi[kk], bl + 2 * kk);
                }
            }
        }

        // ---- P3: acc2 += h2 * Wh2 ----
        #pragma unroll
        for (int half = 0; half < 2; ++half) {
            u32 ahi[2][4], alo[2][4];
            #pragma unroll
            for (int kk = 0; kk < 2; ++kk) {
                ldsm4(ahi[kk], a_addr(sbA, m0, 8 + 2 * half + kk, lane));
                ldsm4(alo[kk], a_addr(sbA, m0, 12 + 2 * half + kk, lane));
            }
            #pragma unroll
            for (int nti = 0; nti < MAXT; ++nti) if (nti < cnt) {
                int nt = nt0 + nti;
                u32 bh[4], bl[4];
                ldsm4(bh, b_addr(sbB2, B2P, nt, 8 + 2 * half, lane));
                ldsm4(bl, b_addr(sbB2, B2P, nt, 12 + 2 * half, lane));
                #pragma unroll
                for (int kk = 0; kk < 2; ++kk) {
                    mma_bf16(acc2[nti], ahi[kk], bh + 2 * kk);
                    mma_bf16(acc2[nti], alo[kk], bh + 2 * kk);
                    mma_bf16(acc2[nti], ahi[kk], bl + 2 * kk);
                }
            }
        }

        __syncthreads();   // all ldmatrix reads of the A tile complete

        epi_l2(acc2, cnt, nt0, lane, jpar, row, b2q, wls, c2, smem, yw, ng);
        epi_l1(acc1, cnt, nt0, lane, jpar, row, b1q, wxq, xv, c1, smem);

        __syncthreads();   // h stores + y partials visible

        if (tid < M_ROWS) {
            float acc = blin_v;
            #pragma unroll
            for (int g2 = 0; g2 < 4; ++g2) acc += yw[tid * 8 + g2];
            out[(size_t)(rb + tid) * T_LEN + t] = acc;
        }
    }
}

extern "C" void kernel_launch(void* const* d_in, const int* in_sizes, int n_in,
                              void* d_out, int out_size) {
    const float* x    = (const float*)d_in[0];
    const float* Wih1 = (const float*)d_in[1];
    const float* Whh1 = (const float*)d_in[2];
    const float* bih1 = (const float*)d_in[3];
    const float* bhh1 = (const float*)d_in[4];
    const float* Wih2 = (const float*)d_in[5];
    const float* Whh2 = (const float*)d_in[6];
    const float* bih2 = (const float*)d_in[7];
    const float* bhh2 = (const float*)d_in[8];
    const float* Wlin = (const float*)d_in[9];
    const float* blin = (const float*)d_in[10];
    float* out = (float*)d_out;

    cudaFuncSetAttribute(lstm2_hmma16_kernel,
                         cudaFuncAttributeMaxDynamicSharedMemorySize, SMEM_TOTAL);

    dim3 grid(NCTA);          // 128 CTAs x 64 rows
    dim3 block(NTHREADS);     // 512 threads = 16 warps
    lstm2_hmma16_kernel<<<grid, block, SMEM_TOTAL>>>(
        x, Wih1, Whh1, bih1, bhh1, Wih2, Whh2, bih2, bhh2, Wlin, blin, out);
}

// round 11
// speedup vs baseline: 1.2136x; 1.2136x over previous
#include <cuda_runtime.h>
#include <cuda_bf16.h>
#include <cstdint>

// ---------------- fixed shapes ----------------
#define NS      51
#define T_LEN   2048
#define B_TOT   8192
#define M_ROWS  64
#define NCTA    (B_TOT / M_ROWS)      // 128
#define NTHREADS 384                  // 4 L1-warps + 8 L2-warps

// SMEM layout (bytes)
#define HPB     272                   // h tile pitch: 128 bf16 (hi|lo) + pad, ldmatrix-clean
#define H1SZ    (64 * HPB)            // 17408
#define B1P     272                   // B1: [208 n][128 bf16] (W1hi|W1lo)
#define B2P     528                   // B2: [208 n][256 bf16] (Wi2hi|Wi2lo|Wh2hi|Wh2lo)

#define OFF_H1_0 0
#define OFF_H1_1 H1SZ
#define OFF_H2   (2 * H1SZ)
#define OFF_B1   (3 * H1SZ)                   // 52224
#define OFF_B2   (OFF_B1 + 208 * B1P)         // 108800
#define OFF_B1Q  (OFF_B2 + 208 * B2P)         // 218624
#define OFF_B2Q  (OFF_B1Q + 832)
#define OFF_WXQ  (OFF_B2Q + 832)
#define OFF_WLS  (OFF_WXQ + 832)              // float[52] + pad
#define OFF_YW   (OFF_WLS + 224)              // float[2][64][2] parity-buffered
#define SMEM_TOTAL (OFF_YW + 1024)            // 221872

typedef uint32_t u32;

// ---------------- helpers (verified in R9) ----------------
__device__ __forceinline__ u32 smem_u32(const void* p) {
    u32 a;
    asm("{ .reg .u64 t; cvta.to.shared.u64 t, %1; cvt.u32.u64 %0, t; }" : "=r"(a) : "l"(p));
    return a;
}
__device__ __forceinline__ void ldsm4(u32* r, u32 addr) {
    asm volatile("ldmatrix.sync.aligned.m8n8.x4.shared.b16 {%0,%1,%2,%3}, [%4];"
                 : "=r"(r[0]), "=r"(r[1]), "=r"(r[2]), "=r"(r[3]) : "r"(addr));
}
__device__ __forceinline__ void mma_bf16(float* c, const u32* a, const u32* b) {
    asm volatile("mma.sync.aligned.m16n8k16.row.col.f32.bf16.bf16.f32 "
                 "{%0,%1,%2,%3}, {%4,%5,%6,%7}, {%8,%9}, {%0,%1,%2,%3};"
                 : "+f"(c[0]), "+f"(c[1]), "+f"(c[2]), "+f"(c[3])
                 : "r"(a[0]), "r"(a[1]), "r"(a[2]), "r"(a[3]), "r"(b[0]), "r"(b[1]));
}
__device__ __forceinline__ float sigm(float v) { return 1.0f / (1.0f + __expf(-v)); }
__device__ __forceinline__ float tanh_fast(float v) { return 2.0f / (1.0f + __expf(-2.0f * v)) - 1.0f; }

// A-fragment (m16k16) inside an h tile (pitch HPB)
__device__ __forceinline__ u32 a_addr(u32 tile, int m0, int kchunk, int lane) {
    int r  = m0 + (lane & 15);
    int cb = kchunk * 32 + ((lane >> 4) << 4);
    return tile + r * HPB + cb;
}
// B-fragment x4 (one n8 tile, two k16 tiles starting at kchunk)
__device__ __forceinline__ u32 b_addr(u32 sbB, int pitch, int nt, int kchunk, int lane) {
    int n  = nt * 8 + (lane & 7);
    int cb = kchunk * 32 + ((lane >> 3) << 4);
    return sbB + n * pitch + cb;
}

// Regroup D-frag gates (verified): lane ends owning (i,f,g,o) of ONE (row,unit)
__device__ __forceinline__ void regroup(const float* C, int lane,
                                        float& gi_, float& gf, float& gg, float& go) {
    float v  = (lane & 1) ? C[0] : C[2];
    float sv = __shfl_xor_sync(0xFFFFFFFFu, v, 1);
    float w  = (lane & 1) ? C[1] : C[3];
    float sw = __shfl_xor_sync(0xFFFFFFFFu, w, 1);
    if (lane & 1) { gi_ = sv;   gf = sw;   gg = C[2]; go = C[3]; }
    else          { gi_ = C[0]; gf = C[1]; gg = sv;   go = sw;  }
}

__device__ __forceinline__ void store_h_tile(char* smem, int tileoff, int row, int j, float h) {
    __nv_bfloat16 hh = __float2bfloat16(h);
    __nv_bfloat16 hl = __float2bfloat16(h - __bfloat162float(hh));
    *(__nv_bfloat16*)(smem + tileoff + row * HPB + j * 2)       = hh;
    *(__nv_bfloat16*)(smem + tileoff + row * HPB + 128 + j * 2) = hl;
}

__global__ __launch_bounds__(NTHREADS, 1)
void lstm2_ws_kernel(
    const float* __restrict__ x,      // [B, T]
    const float* __restrict__ Wih1,   // [204, 1]
    const float* __restrict__ Whh1,   // [204, 51]
    const float* __restrict__ bih1,
    const float* __restrict__ bhh1,
    const float* __restrict__ Wih2,   // [204, 51]
    const float* __restrict__ Whh2,   // [204, 51]
    const float* __restrict__ bih2,
    const float* __restrict__ bhh2,
    const float* __restrict__ Wlin,   // [1, 51]
    const float* __restrict__ blin,
    float* __restrict__ out)          // [B, T]
{
    extern __shared__ char smem[];
    const u32 sb = smem_u32(smem);
    const int tid  = threadIdx.x;
    const int wid  = tid >> 5;
    const int lane = tid & 31;
    const int rb   = blockIdx.x * M_ROWS;

    for (int i = tid; i < SMEM_TOTAL / 4; i += NTHREADS) ((u32*)smem)[i] = 0;
    __syncthreads();

    float4* b1q = (float4*)(smem + OFF_B1Q);
    float4* b2q = (float4*)(smem + OFF_B2Q);
    float4* wxq = (float4*)(smem + OFF_WXQ);
    float*  wls = (float*)(smem + OFF_WLS);
    float*  yw  = (float*)(smem + OFF_YW);    // [2][64][2]

    // ---- stage weights: B row n = 4*j + gi, hi/lo bf16 split ----
    for (int idx = tid; idx < 208 * NS; idx += NTHREADS) {
        int n = idx / NS, m = idx % NS;
        int j = n >> 2, gi = n & 3;
        if (j < NS) {
            int g = gi * NS + j;
            float w1  = Whh1[g * NS + m];
            float wi2 = Wih2[g * NS + m];
            float wh2 = Whh2[g * NS + m];
            __nv_bfloat16 h, l;
            h = __float2bfloat16(w1);  l = __float2bfloat16(w1 - __bfloat162float(h));
            *(__nv_bfloat16*)(smem + OFF_B1 + n * B1P + m * 2)        = h;
            *(__nv_bfloat16*)(smem + OFF_B1 + n * B1P + (64 + m) * 2) = l;
            h = __float2bfloat16(wi2); l = __float2bfloat16(wi2 - __bfloat162float(h));
            *(__nv_bfloat16*)(smem + OFF_B2 + n * B2P + m * 2)        = h;
            *(__nv_bfloat16*)(smem + OFF_B2 + n * B2P + (64 + m) * 2) = l;
            h = __float2bfloat16(wh2); l = __float2bfloat16(wh2 - __bfloat162float(h));
            *(__nv_bfloat16*)(smem + OFF_B2 + n * B2P + (128 + m) * 2) = h;
            *(__nv_bfloat16*)(smem + OFF_B2 + n * B2P + (192 + m) * 2) = l;
        }
    }
    for (int j = tid; j < NS; j += NTHREADS) {
        b1q[j] = make_float4(bih1[j] + bhh1[j], bih1[j + NS] + bhh1[j + NS],
                             bih1[j + 2 * NS] + bhh1[j + 2 * NS], bih1[j + 3 * NS] + bhh1[j + 3 * NS]);
        b2q[j] = make_float4(bih2[j] + bhh2[j], bih2[j + NS] + bhh2[j + NS],
                             bih2[j + 2 * NS] + bhh2[j + 2 * NS], bih2[j + 3 * NS] + bhh2[j + 3 * NS]);
        wxq[j] = make_float4(Wih1[j], Wih1[j + NS], Wih1[j + 2 * NS], Wih1[j + 3 * NS]);
        wls[j] = Wlin[j];
    }
    __syncthreads();

    const float blin_v = blin[0];
    const int jpar = (lane >> 1) & 1;
    const u32 sbB1 = sb + OFF_B1;
    const u32 sbB2 = sb + OFF_B2;
    const u32 h2t  = sb + OFF_H2;

    const bool isA = (wid < 4);
    // Group A: warp = one m-tile; lane = one row
    const int m0A  = 16 * wid;
    const int rowA = m0A + (lane >> 2) + 8 * (lane & 1);
    // Group B: 4 m x 2 n
    const int widB = wid - 4;
    const int m0B  = 16 * (widB >> 1);
    const int ngB  = widB & 1;
    const int ntB0 = 13 * ngB;
    const int rowB = m0B + (lane >> 2) + 8 * (lane & 1);

    float c1[26], c2[13];
    #pragma unroll
    for (int i = 0; i < 26; ++i) c1[i] = 0.0f;
    #pragma unroll
    for (int i = 0; i < 13; ++i) c2[i] = 0.0f;

    // ---- prologue: A computes h1(0) directly (h=0, c=0) into buffer 0 ----
    if (isA) {
        float xv0 = __ldg(&x[(size_t)(rb + rowA) * T_LEN]);
        #pragma unroll
        for (int nt = 0; nt < 26; ++nt) {
            int j = 2 * nt + jpar;
            if (j < NS) {
                float4 b  = b1q[j];
                float4 wx = wxq[j];
                float pi = fmaf(xv0, wx.x, b.x);
                float pg = fmaf(xv0, wx.z, b.z);
                float po = fmaf(xv0, wx.w, b.w);
                float cn = sigm(pi) * tanh_fast(pg);
                c1[nt] = cn;
                store_h_tile(smem, OFF_H1_0, rowA, j, sigm(po) * tanh_fast(cn));
            }
        }
    }
    __syncthreads();

    // ---- main loop: step t: A -> h1(t+1), B -> h2(t) + y(t) ----
    for (int t = 0; t < T_LEN; ++t) {
        const int cur = t & 1;
        const u32 h1cur   = sb + (cur ? OFF_H1_1 : OFF_H1_0);
        const int h1nxtOf = cur ? OFF_H1_0 : OFF_H1_1;

        if (isA) {
            // finalize y(t-1) (yw parity cur^1, written by B last step)
            if (tid < M_ROWS && t > 0) {
                const float* ywp = yw + (cur ^ 1) * 128;
                out[(size_t)(rb + tid) * T_LEN + (t - 1)] =
                    blin_v + ywp[tid * 2] + ywp[tid * 2 + 1];
            }
            float xv = (t + 1 < T_LEN)
                     ? __ldg(&x[(size_t)(rb + rowA) * T_LEN + t + 1]) : 0.0f;

            #pragma unroll
            for (int p = 0; p < 2; ++p) {
                float acc[13][4];
                #pragma unroll
                for (int i = 0; i < 13; ++i)
                    #pragma unroll
                    for (int q = 0; q < 4; ++q) acc[i][q] = 0.0f;

                #pragma unroll
                for (int half = 0; half < 2; ++half) {
                    u32 ahi[2][4], alo[2][4];
                    #pragma unroll
                    for (int kk = 0; kk < 2; ++kk) {
                        ldsm4(ahi[kk], a_addr(h1cur, m0A, 2 * half + kk, lane));
                        ldsm4(alo[kk], a_addr(h1cur, m0A, 4 + 2 * half + kk, lane));
                    }
                    #pragma unroll
                    for (int nti = 0; nti < 13; ++nti) {
                        int nt = 13 * p + nti;
                        u32 bh[4], bl[4];
                        ldsm4(bh, b_addr(sbB1, B1P, nt, 2 * half, lane));
                        ldsm4(bl, b_addr(sbB1, B1P, nt, 4 + 2 * half, lane));
                        #pragma unroll
                        for (int kk = 0; kk < 2; ++kk) {
                            mma_bf16(acc[nti], ahi[kk], bh + 2 * kk);
                            mma_bf16(acc[nti], alo[kk], bh + 2 * kk);
                            mma_bf16(acc[nti], ahi[kk], bl + 2 * kk);
                        }
                    }
                }
                // epilogue pass p -> h1(t+1) in next buffer
                #pragma unroll
                for (int nti = 0; nti < 13; ++nti) {
                    float gi_, gf, gg, go;
                    regroup(acc[nti], lane, gi_, gf, gg, go);
                    int nt = 13 * p + nti;
                    int j = 2 * nt + jpar;
                    float4 b  = b1q[j];
                    float4 wx = wxq[j];
                    float pi = fmaf(xv, wx.x, gi_ + b.x);
                    float pf = fmaf(xv, wx.y, gf + b.y);
                    float pg = fmaf(xv, wx.z, gg + b.z);
                    float po = fmaf(xv, wx.w, go + b.w);
                    float cn = fmaf(sigm(pf), c1[nt], sigm(pi) * tanh_fast(pg));
                    c1[nt] = cn;
                    float h = sigm(po) * tanh_fast(cn);
                    if (j < NS) store_h_tile(smem, h1nxtOf, rowA, j, h);
                }
            }
        } else {
            // ----- Group B: h2(t) = L2(h1(t), h2(t-1)) -----
            float acc[13][4];
            #pragma unroll
            for (int i = 0; i < 13; ++i)
                #pragma unroll
                for (int q = 0; q < 4; ++q) acc[i][q] = 0.0f;

            #pragma unroll
            for (int half = 0; half < 2; ++half) {
                u32 a1h[2][4], a1l[2][4], a2h[2][4], a2l[2][4];
                #pragma unroll
                for (int kk = 0; kk < 2; ++kk) {
                    ldsm4(a1h[kk], a_addr(h1cur, m0B, 2 * half + kk, lane));
                    ldsm4(a1l[kk], a_addr(h1cur, m0B, 4 + 2 * half + kk, lane));
                    ldsm4(a2h[kk], a_addr(h2t,   m0B, 2 * half + kk, lane));
                    ldsm4(a2l[kk], a_addr(h2t,   m0B, 4 + 2 * half + kk, lane));
                }
                #pragma unroll
                for (int nti = 0; nti < 13; ++nti) {
                    int nt = ntB0 + nti;
                    u32 bih[4], bil[4], bhh[4], bhl[4];
                    ldsm4(bih, b_addr(sbB2, B2P, nt, 2 * half, lane));
                    ldsm4(bil, b_addr(sbB2, B2P, nt, 4 + 2 * half, lane));
                    ldsm4(bhh, b_addr(sbB2, B2P, nt, 8 + 2 * half, lane));
                    ldsm4(bhl, b_addr(sbB2, B2P, nt, 12 + 2 * half, lane));
                    #pragma unroll
                    for (int kk = 0; kk < 2; ++kk) {
                        mma_bf16(acc[nti], a1h[kk], bih + 2 * kk);
                        mma_bf16(acc[nti], a1l[kk], bih + 2 * kk);
                        mma_bf16(acc[nti], a1h[kk], bil + 2 * kk);
                        mma_bf16(acc[nti], a2h[kk], bhh + 2 * kk);
                        mma_bf16(acc[nti], a2l[kk], bhh + 2 * kk);
                        mma_bf16(acc[nti], a2h[kk], bhl + 2 * kk);
                    }
                }
            }
            asm volatile("bar.sync 1, 256;" ::: "memory");   // B-only: h2 reads done

            float yp = 0.0f;
            #pragma unroll
            for (int nti = 0; nti < 13; ++nti) {
                float gi_, gf, gg, go;
                regroup(acc[nti], lane, gi_, gf, gg, go);
                int j = 2 * (ntB0 + nti) + jpar;
                float4 b = b2q[j];
                float pi = gi_ + b.x, pf = gf + b.y, pg = gg + b.z, po = go + b.w;
                float cn = fmaf(sigm(pf), c2[nti], sigm(pi) * tanh_fast(pg));
                c2[nti] = cn;
                float h = sigm(po) * tanh_fast(cn);
                if (j < NS) {
                    store_h_tile(smem, OFF_H2, rowB, j, h);
                    yp = fmaf(wls[j], h, yp);
                }
            }
            float ys = yp + __shfl_xor_sync(0xFFFFFFFFu, yp, 2);
            if (!(lane & 2)) yw[cur * 128 + rowB * 2 + ngB] = ys;
        }
        __syncthreads();   // single cross-group barrier per step
    }

    // ---- final projection: y(T-1) in parity (T-1)&1 ----
    if (tid < M_ROWS) {
        const float* ywp = yw + ((T_LEN - 1) & 1) * 128;
        out[(size_t)(rb + tid) * T_LEN + (T_LEN - 1)] =
            blin_v + ywp[tid * 2] + ywp[tid * 2 + 1];
    }
}

extern "C" void kernel_launch(void* const* d_in, const int* in_sizes, int n_in,
                              void* d_out, int out_size) {
    const float* x    = (const float*)d_in[0];
    const float* Wih1 = (const float*)d_in[1];
    const float* Whh1 = (const float*)d_in[2];
    const float* bih1 = (const float*)d_in[3];
    const float* bhh1 = (const float*)d_in[4];
    const float* Wih2 = (const float*)d_in[5];
    const float* Whh2 = (const float*)d_in[6];
    const float* bih2 = (const float*)d_in[7];
    const float* bhh2 = (const float*)d_in[8];
    const float* Wlin = (const float*)d_in[9];
    const float* blin = (const float*)d_in[10];
    float* out = (float*)d_out;

    cudaFuncSetAttribute(lstm2_ws_kernel,
                         cudaFuncAttributeMaxDynamicSharedMemorySize, SMEM_TOTAL);

    dim3 grid(NCTA);          // 128 CTAs x 64 rows
    dim3 block(NTHREADS);     // 384 threads: 4 L1-warps + 8 L2-warps
    lstm2_ws_kernel<<<grid, block, SMEM_TOTAL>>>(
        x, Wih1, Whh1, bih1, bhh1, Wih2, Whh2, bih2, bhh2, Wlin, blin, out);
}

// round 12
// speedup vs baseline: 1.3960x; 1.1502x over previous
#include <cuda_runtime.h>
#include <cuda_bf16.h>
#include <cstdint>

// ---------------- fixed shapes ----------------
#define NS      51
#define T_LEN   2048
#define B_TOT   8192
#define M_ROWS  64
#define NCTA    (B_TOT / M_ROWS)      // 128
#define NTHREADS 384                  // 12 warps = 2 m-groups x 6 n-groups

// SMEM layout (bytes)
#define HPB     272                   // h tile pitch: 128 bf16 (hi|lo) + pad
#define HTSZ    (64 * HPB)            // 17408 per h tile
#define B1P     272                   // B1: [208 n][128 bf16] (W1hi|W1lo)
#define B2P     528                   // B2: [208 n][256 bf16] (Wi2hi|Wi2lo|Wh2hi|Wh2lo)

#define OFF_H1_0 0
#define OFF_H1_1 HTSZ                 // 17408
#define OFF_H2   (2 * HTSZ)           // 34816
#define OFF_B1   (3 * HTSZ)           // 52224
#define OFF_B2   (OFF_B1 + 208 * B1P) // 108800
#define OFF_B1Q  (OFF_B2 + 208 * B2P) // 218624
#define OFF_B2Q  (OFF_B1Q + 832)
#define OFF_WXQ  (OFF_B2Q + 832)
#define OFF_WLS  (OFF_WXQ + 832)      // float[52] + pad
#define OFF_YW   (OFF_WLS + 224)      // float[64][8]
#define SMEM_TOTAL (OFF_YW + 64 * 8 * 4)   // 223392

typedef uint32_t u32;

// ---------------- helpers (fragment maps verified in R9) ----------------
__device__ __forceinline__ u32 smem_u32(const void* p) {
    u32 a;
    asm("{ .reg .u64 t; cvta.to.shared.u64 t, %1; cvt.u32.u64 %0, t; }" : "=r"(a) : "l"(p));
    return a;
}
__device__ __forceinline__ void ldsm4(u32* r, u32 addr) {
    asm volatile("ldmatrix.sync.aligned.m8n8.x4.shared.b16 {%0,%1,%2,%3}, [%4];"
                 : "=r"(r[0]), "=r"(r[1]), "=r"(r[2]), "=r"(r[3]) : "r"(addr));
}
__device__ __forceinline__ void mma_bf16(float* c, const u32* a, const u32* b) {
    asm volatile("mma.sync.aligned.m16n8k16.row.col.f32.bf16.bf16.f32 "
                 "{%0,%1,%2,%3}, {%4,%5,%6,%7}, {%8,%9}, {%0,%1,%2,%3};"
                 : "+f"(c[0]), "+f"(c[1]), "+f"(c[2]), "+f"(c[3])
                 : "r"(a[0]), "r"(a[1]), "r"(a[2]), "r"(a[3]), "r"(b[0]), "r"(b[1]));
}
__device__ __forceinline__ float sigm(float v) { return 1.0f / (1.0f + __expf(-v)); }
__device__ __forceinline__ float tanh_fast(float v) { return 2.0f / (1.0f + __expf(-2.0f * v)) - 1.0f; }

// A-fragment (m16k16) in an h tile (pitch HPB); kchunk 0-3 = hi, 4-7 = lo
__device__ __forceinline__ u32 a_addr(u32 tile, int m0, int kchunk, int lane) {
    int r  = m0 + (lane & 15);
    int cb = kchunk * 32 + ((lane >> 4) << 4);
    return tile + r * HPB + cb;
}
// B-fragment x4 (one n8 tile, two k16 tiles starting at kchunk)
__device__ __forceinline__ u32 b_addr(u32 sbB, int pitch, int nt, int kchunk, int lane) {
    int n  = nt * 8 + (lane & 7);
    int cb = kchunk * 32 + ((lane >> 3) << 4);
    return sbB + n * pitch + cb;
}

// Regroup D-frag gates (verified): lane ends owning (i,f,g,o) of ONE (row,unit)
__device__ __forceinline__ void regroup(const float* C, int lane,
                                        float& gi_, float& gf, float& gg, float& go) {
    float v  = (lane & 1) ? C[0] : C[2];
    float sv = __shfl_xor_sync(0xFFFFFFFFu, v, 1);
    float w  = (lane & 1) ? C[1] : C[3];
    float sw = __shfl_xor_sync(0xFFFFFFFFu, w, 1);
    if (lane & 1) { gi_ = sv;   gf = sw;   gg = C[2]; go = C[3]; }
    else          { gi_ = C[0]; gf = C[1]; gg = sv;   go = sw;  }
}

__device__ __forceinline__ void store_h_tile(char* smem, int tileoff, int row, int j, float h) {
    __nv_bfloat16 hh = __float2bfloat16(h);
    __nv_bfloat16 hl = __float2bfloat16(h - __bfloat162float(hh));
    *(__nv_bfloat16*)(smem + tileoff + row * HPB + j * 2)       = hh;
    *(__nv_bfloat16*)(smem + tileoff + row * HPB + 128 + j * 2) = hl;
}

// Layer-1 epilogue: writes h1 into tile h1off
__device__ __forceinline__ void epi_l1(
    float acc[2][5][4], int cnt, int nt0, int lane, int jpar, const int* rows,
    const float4* b1q, const float4* wxq, const float* xv,
    float c1[2][5], char* smem, int h1off)
{
    #pragma unroll
    for (int mt = 0; mt < 2; ++mt) {
        #pragma unroll
        for (int nti = 0; nti < 5; ++nti) if (nti < cnt) {
            float gi_, gf, gg, go;
            regroup(acc[mt][nti], lane, gi_, gf, gg, go);
            int j = 2 * (nt0 + nti) + jpar;
            float4 b  = b1q[j];
            float4 wx = wxq[j];
            float pi = fmaf(xv[mt], wx.x, gi_ + b.x);
            float pf = fmaf(xv[mt], wx.y, gf + b.y);
            float pg = fmaf(xv[mt], wx.z, gg + b.z);
            float po = fmaf(xv[mt], wx.w, go + b.w);
            float cn = fmaf(sigm(pf), c1[mt][nti], sigm(pi) * tanh_fast(pg));
            c1[mt][nti] = cn;
            float h = sigm(po) * tanh_fast(cn);
            if (j < NS) store_h_tile(smem, h1off, rows[mt], j, h);
        }
    }
}

// Layer-2 epilogue: writes h2 (in place) + y partials
__device__ __forceinline__ void epi_l2(
    float acc[2][5][4], int cnt, int nt0, int lane, int jpar, const int* rows,
    const float4* b2q, const float* wls,
    float c2[2][5], char* smem, float* yw, int ng)
{
    #pragma unroll
    for (int mt = 0; mt < 2; ++mt) {
        float yp = 0.0f;
        #pragma unroll
        for (int nti = 0; nti < 5; ++nti) if (nti < cnt) {
            float gi_, gf, gg, go;
            regroup(acc[mt][nti], lane, gi_, gf, gg, go);
            int j = 2 * (nt0 + nti) + jpar;
            float4 b = b2q[j];
            float pi = gi_ + b.x, pf = gf + b.y, pg = gg + b.z, po = go + b.w;
            float cn = fmaf(sigm(pf), c2[mt][nti], sigm(pi) * tanh_fast(pg));
            c2[mt][nti] = cn;
            float h = sigm(po) * tanh_fast(cn);
            if (j < NS) {
                store_h_tile(smem, OFF_H2, rows[mt], j, h);
                yp = fmaf(wls[j], h, yp);
            }
        }
        float ys = yp + __shfl_xor_sync(0xFFFFFFFFu, yp, 2);
        if (!(lane & 2)) yw[rows[mt] * 8 + ng] = ys;
    }
}

__global__ __launch_bounds__(NTHREADS, 1)
void lstm2_hmma12d_kernel(
    const float* __restrict__ x,      // [B, T]
    const float* __restrict__ Wih1,   // [204, 1]
    const float* __restrict__ Whh1,   // [204, 51]
    const float* __restrict__ bih1,
    const float* __restrict__ bhh1,
    const float* __restrict__ Wih2,   // [204, 51]
    const float* __restrict__ Whh2,   // [204, 51]
    const float* __restrict__ bih2,
    const float* __restrict__ bhh2,
    const float* __restrict__ Wlin,   // [1, 51]
    const float* __restrict__ blin,
    float* __restrict__ out)          // [B, T]
{
    extern __shared__ char smem[];
    const u32 sb = smem_u32(smem);
    const int tid  = threadIdx.x;
    const int wid  = tid >> 5;
    const int lane = tid & 31;
    const int mg   = wid / 6;                 // m-group 0/1 (rows 0-31 / 32-63)
    const int ng   = wid % 6;                 // n-group
    const int cnt  = (ng < 2) ? 5 : 4;
    const int nt0  = (ng < 2) ? 5 * ng : 10 + 4 * (ng - 2);
    const int rb   = blockIdx.x * M_ROWS;
    const int gtid = tid - 192 * mg;          // tid within my m-group (0..191)

    for (int i = tid; i < SMEM_TOTAL / 4; i += NTHREADS) ((u32*)smem)[i] = 0;
    __syncthreads();

    float4* b1q = (float4*)(smem + OFF_B1Q);
    float4* b2q = (float4*)(smem + OFF_B2Q);
    float4* wxq = (float4*)(smem + OFF_WXQ);
    float*  wls = (float*)(smem + OFF_WLS);
    float*  yw  = (float*)(smem + OFF_YW);

    // ---- stage weights: B row n = 4*j + gi, hi/lo bf16 split ----
    for (int idx = tid; idx < 208 * NS; idx += NTHREADS) {
        int n = idx / NS, m = idx % NS;
        int j = n >> 2, gi = n & 3;
        if (j < NS) {
            int g = gi * NS + j;
            float w1  = Whh1[g * NS + m];
            float wi2 = Wih2[g * NS + m];
            float wh2 = Whh2[g * NS + m];
            __nv_bfloat16 h, l;
            h = __float2bfloat16(w1);  l = __float2bfloat16(w1 - __bfloat162float(h));
            *(__nv_bfloat16*)(smem + OFF_B1 + n * B1P + m * 2)        = h;
            *(__nv_bfloat16*)(smem + OFF_B1 + n * B1P + (64 + m) * 2) = l;
            h = __float2bfloat16(wi2); l = __float2bfloat16(wi2 - __bfloat162float(h));
            *(__nv_bfloat16*)(smem + OFF_B2 + n * B2P + m * 2)        = h;
            *(__nv_bfloat16*)(smem + OFF_B2 + n * B2P + (64 + m) * 2) = l;
            h = __float2bfloat16(wh2); l = __float2bfloat16(wh2 - __bfloat162float(h));
            *(__nv_bfloat16*)(smem + OFF_B2 + n * B2P + (128 + m) * 2) = h;
            *(__nv_bfloat16*)(smem + OFF_B2 + n * B2P + (192 + m) * 2) = l;
        }
    }
    for (int j = tid; j < NS; j += NTHREADS) {
        b1q[j] = make_float4(bih1[j] + bhh1[j], bih1[j + NS] + bhh1[j + NS],
                             bih1[j + 2 * NS] + bhh1[j + 2 * NS], bih1[j + 3 * NS] + bhh1[j + 3 * NS]);
        b2q[j] = make_float4(bih2[j] + bhh2[j], bih2[j + NS] + bhh2[j + NS],
                             bih2[j + 2 * NS] + bhh2[j + 2 * NS], bih2[j + 3 * NS] + bhh2[j + 3 * NS]);
        wxq[j] = make_float4(Wih1[j], Wih1[j + NS], Wih1[j + 2 * NS], Wih1[j + 3 * NS]);
        wls[j] = Wlin[j];
    }
    __syncthreads();

    const float blin_v = blin[0];
    const int m0base = 32 * mg;
    const int rbase  = m0base + (lane >> 2) + 8 * (lane & 1);
    const int rows[2] = {rbase, rbase + 16};
    const int jpar = (lane >> 1) & 1;
    const u32 sbB1 = sb + OFF_B1;
    const u32 sbB2 = sb + OFF_B2;
    const u32 h2t  = sb + OFF_H2;
    const int barid = mg + 1;

    float c1[2][5], c2[2][5];
    #pragma unroll
    for (int mt = 0; mt < 2; ++mt)
        #pragma unroll
        for (int i = 0; i < 5; ++i) { c1[mt][i] = 0.0f; c2[mt][i] = 0.0f; }

    // ---- prologue: h1(0) = L1(x(0), h=0, c=0) into tile H1_0 ----
    {
        float acc0[2][5][4];
        #pragma unroll
        for (int mt = 0; mt < 2; ++mt)
            #pragma unroll
            for (int i = 0; i < 5; ++i)
                #pragma unroll
                for (int q = 0; q < 4; ++q) acc0[mt][i][q] = 0.0f;
        float xv0[2];
        #pragma unroll
        for (int mt = 0; mt < 2; ++mt)
            xv0[mt] = __ldg(&x[(size_t)(rb + rows[mt]) * T_LEN]);
        epi_l1(acc0, cnt, nt0, lane, jpar, rows, b1q, wxq, xv0, c1, smem, OFF_H1_0);
    }
    __syncthreads();

    // ---- main loop: step t uses {h1(t) in buf t&1, h2(t-1) in H2} ----
    for (int t = 0; t < T_LEN; ++t) {
        const u32 h1cur   = sb + ((t & 1) ? OFF_H1_1 : OFF_H1_0);
        const int h1nxtOf = (t & 1) ? OFF_H1_0 : OFF_H1_1;

        // y(t-1) store, overlapped with MMA phase (yw stable until post-bar epi_l2)
        if (gtid < 32 && t > 0) {
            int r = m0base + gtid;
            float acc = blin_v;
            #pragma unroll
            for (int g2 = 0; g2 < 6; ++g2) acc += yw[r * 8 + g2];
            out[(size_t)(rb + r) * T_LEN + (t - 1)] = acc;
        }

        float xv[2];
        #pragma unroll
        for (int mt = 0; mt < 2; ++mt)
            xv[mt] = (t + 1 < T_LEN)
                   ? __ldg(&x[(size_t)(rb + rows[mt]) * T_LEN + t + 1]) : 0.0f;

        float acc1[2][5][4], acc2[2][5][4];
        #pragma unroll
        for (int mt = 0; mt < 2; ++mt)
            #pragma unroll
            for (int i = 0; i < 5; ++i)
                #pragma unroll
                for (int q = 0; q < 4; ++q) { acc1[mt][i][q] = 0.0f; acc2[mt][i][q] = 0.0f; }

        // ---- P12: acc1 += h1*W1 ; acc2 += h1*Wi2  (shared h1 A-frags) ----
        #pragma unroll
        for (int half = 0; half < 2; ++half) {
            u32 ahi[2][2][4], alo[2][2][4];
            #pragma unroll
            for (int mt = 0; mt < 2; ++mt)
                #pragma unroll
                for (int kk = 0; kk < 2; ++kk) {
                    ldsm4(ahi[mt][kk], a_addr(h1cur, m0base + 16 * mt, 2 * half + kk, lane));
                    ldsm4(alo[mt][kk], a_addr(h1cur, m0base + 16 * mt, 4 + 2 * half + kk, lane));
                }
            #pragma unroll
            for (int nti = 0; nti < 5; ++nti) if (nti < cnt) {
                int nt = nt0 + nti;
                u32 bh[4], bl[4];
                ldsm4(bh, b_addr(sbB1, B1P, nt, 2 * half, lane));
                ldsm4(bl, b_addr(sbB1, B1P, nt, 4 + 2 * half, lane));
                #pragma unroll
                for (int mt = 0; mt < 2; ++mt)
                    #pragma unroll
                    for (int kk = 0; kk < 2; ++kk) {
                        mma_bf16(acc1[mt][nti], ahi[mt][kk], bh + 2 * kk);
                        mma_bf16(acc1[mt][nti], alo[mt][kk], bh + 2 * kk);
                        mma_bf16(acc1[mt][nti], ahi[mt][kk], bl + 2 * kk);
                    }
                ldsm4(bh, b_addr(sbB2, B2P, nt, 2 * half, lane));
                ldsm4(bl, b_addr(sbB2, B2P, nt, 4 + 2 * half, lane));
                #pragma unroll
                for (int mt = 0; mt < 2; ++mt)
                    #pragma unroll
                    for (int kk = 0; kk < 2; ++kk) {
                        mma_bf16(acc2[mt][nti], ahi[mt][kk], bh + 2 * kk);
                        mma_bf16(acc2[mt][nti], alo[mt][kk], bh + 2 * kk);
                        mma_bf16(acc2[mt][nti], ahi[mt][kk], bl + 2 * kk);
                    }
            }
        }

        // ---- P3: acc2 += h2 * Wh2 ----
        #pragma unroll
        for (int half = 0; half < 2; ++half) {
            u32 ahi[2][2][4], alo[2][2][4];
            #pragma unroll
            for (int mt = 0; mt < 2; ++mt)
                #pragma unroll
                for (int kk = 0; kk < 2; ++kk) {
                    ldsm4(ahi[mt][kk], a_addr(h2t, m0base + 16 * mt, 2 * half + kk, lane));
                    ldsm4(alo[mt][kk], a_addr(h2t, m0base + 16 * mt, 4 + 2 * half + kk, lane));
                }
            #pragma unroll
            for (int nti = 0; nti < 5; ++nti) if (nti < cnt) {
                int nt = nt0 + nti;
                u32 bh[4], bl[4];
                ldsm4(bh, b_addr(sbB2, B2P, nt, 8 + 2 * half, lane));
                ldsm4(bl, b_addr(sbB2, B2P, nt, 12 + 2 * half, lane));
                #pragma unroll
                for (int mt = 0; mt < 2; ++mt)
                    #pragma unroll
                    for (int kk = 0; kk < 2; ++kk) {
                        mma_bf16(acc2[mt][nti], ahi[mt][kk], bh + 2 * kk);
                        mma_bf16(acc2[mt][nti], alo[mt][kk], bh + 2 * kk);
                        mma_bf16(acc2[mt][nti], ahi[mt][kk], bl + 2 * kk);
                    }
            }
        }

        // group barrier: all my-group reads of h2 (and yw) done
        asm volatile("bar.sync %0, 192;" :: "r"(barid) : "memory");

        epi_l2(acc2, cnt, nt0, lane, jpar, rows, b2q, wls, c2, smem, yw, ng);
        epi_l1(acc1, cnt, nt0, lane, jpar, rows, b1q, wxq, xv, c1, smem, h1nxtOf);

        // group barrier: my-group h1(t+1), h2(t), yw(t) writes visible
        asm volatile("bar.sync %0, 192;" :: "r"(barid) : "memory");
    }

    // ---- final projection: y(T-1) ----
    if (gtid < 32) {
        int r = m0base + gtid;
        float acc = blin_v;
        #pragma unroll
        for (int g2 = 0; g2 < 6; ++g2) acc += yw[r * 8 + g2];
        out[(size_t)(rb + r) * T_LEN + (T_LEN - 1)] = acc;
    }
}

extern "C" void kernel_launch(void* const* d_in, const int* in_sizes, int n_in,
                              void* d_out, int out_size) {
    const float* x    = (const float*)d_in[0];
    const float* Wih1 = (const float*)d_in[1];
    const float* Whh1 = (const float*)d_in[2];
    const float* bih1 = (const float*)d_in[3];
    const float* bhh1 = (const float*)d_in[4];
    const float* Wih2 = (const float*)d_in[5];
    const float* Whh2 = (const float*)d_in[6];
    const float* bih2 = (const float*)d_in[7];
    const float* bhh2 = (const float*)d_in[8];
    const float* Wlin = (const float*)d_in[9];
    const float* blin = (const float*)d_in[10];
    float* out = (float*)d_out;

    cudaFuncSetAttribute(lstm2_hmma12d_kernel,
                         cudaFuncAttributeMaxDynamicSharedMemorySize, SMEM_TOTAL);

    dim3 grid(NCTA);          // 128 CTAs x 64 rows
    dim3 block(NTHREADS);     // 384 threads = 12 warps
    lstm2_hmma12d_kernel<<<grid, block, SMEM_TOTAL>>>(
        x, Wih1, Whh1, bih1, bhh1, Wih2, Whh2, bih2, bhh2, Wlin, blin, out);
}

// round 13
// speedup vs baseline: 1.6211x; 1.1613x over previous
#include <cuda_runtime.h>
#include <cuda_bf16.h>
#include <cstdint>

// ---------------- fixed shapes ----------------
#define NS      51
#define T_LEN   2048
#define B_TOT   8192
#define M_ROWS  64
#define NCTA    (B_TOT / M_ROWS)      // 128
#define NTHREADS 384                  // 12 warps = 2 m-groups x 6 n-groups

// SMEM layout (bytes)
#define HPB     272                   // h tile pitch: 128 bf16 (hi|lo) + pad
#define HTSZ    (64 * HPB)            // 17408 per h tile
#define B1P     272                   // B1: [208 n][128 bf16] (W1hi|W1lo)
#define B2P     528                   // B2: [208 n][256 bf16] (Wi2hi|Wi2lo|Wh2hi|Wh2lo)

#define OFF_H1_0 0
#define OFF_H1_1 HTSZ                 // 17408
#define OFF_H2   (2 * HTSZ)           // 34816
#define OFF_B1   (3 * HTSZ)           // 52224
#define OFF_B2   (OFF_B1 + 208 * B1P) // 108800
#define OFF_B1Q  (OFF_B2 + 208 * B2P) // 218624
#define OFF_B2Q  (OFF_B1Q + 832)
#define OFF_WXQ  (OFF_B2Q + 832)
#define OFF_WLS  (OFF_WXQ + 832)      // float[52] + pad
#define OFF_YW   (OFF_WLS + 224)      // float[64][8]
#define SMEM_TOTAL (OFF_YW + 64 * 8 * 4)   // 223392

typedef uint32_t u32;

// ---------------- helpers (fragment maps verified in R9) ----------------
__device__ __forceinline__ u32 smem_u32(const void* p) {
    u32 a;
    asm("{ .reg .u64 t; cvta.to.shared.u64 t, %1; cvt.u32.u64 %0, t; }" : "=r"(a) : "l"(p));
    return a;
}
__device__ __forceinline__ void ldsm4(u32* r, u32 addr) {
    asm volatile("ldmatrix.sync.aligned.m8n8.x4.shared.b16 {%0,%1,%2,%3}, [%4];"
                 : "=r"(r[0]), "=r"(r[1]), "=r"(r[2]), "=r"(r[3]) : "r"(addr));
}
__device__ __forceinline__ void mma_bf16(float* c, const u32* a, const u32* b) {
    asm volatile("mma.sync.aligned.m16n8k16.row.col.f32.bf16.bf16.f32 "
                 "{%0,%1,%2,%3}, {%4,%5,%6,%7}, {%8,%9}, {%0,%1,%2,%3};"
                 : "+f"(c[0]), "+f"(c[1]), "+f"(c[2]), "+f"(c[3])
                 : "r"(a[0]), "r"(a[1]), "r"(a[2]), "r"(a[3]), "r"(b[0]), "r"(b[1]));
}
__device__ __forceinline__ float sigm(float v) { return 1.0f / (1.0f + __expf(-v)); }
__device__ __forceinline__ float tanh_fast(float v) { return 2.0f / (1.0f + __expf(-2.0f * v)) - 1.0f; }

// A-fragment (m16k16) in an h tile (pitch HPB); kchunk 0-3 = hi, 4-7 = lo
__device__ __forceinline__ u32 a_addr(u32 tile, int m0, int kchunk, int lane) {
    int r  = m0 + (lane & 15);
    int cb = kchunk * 32 + ((lane >> 4) << 4);
    return tile + r * HPB + cb;
}
// B-fragment x4 (one n8 tile, two k16 tiles starting at kchunk)
__device__ __forceinline__ u32 b_addr(u32 sbB, int pitch, int nt, int kchunk, int lane) {
    int n  = nt * 8 + (lane & 7);
    int cb = kchunk * 32 + ((lane >> 3) << 4);
    return sbB + n * pitch + cb;
}

// Regroup D-frag gates (verified): lane ends owning (i,f,g,o) of ONE (row,unit)
__device__ __forceinline__ void regroup(const float* C, int lane,
                                        float& gi_, float& gf, float& gg, float& go) {
    float v  = (lane & 1) ? C[0] : C[2];
    float sv = __shfl_xor_sync(0xFFFFFFFFu, v, 1);
    float w  = (lane & 1) ? C[1] : C[3];
    float sw = __shfl_xor_sync(0xFFFFFFFFu, w, 1);
    if (lane & 1) { gi_ = sv;   gf = sw;   gg = C[2]; go = C[3]; }
    else          { gi_ = C[0]; gf = C[1]; gg = sv;   go = sw;  }
}

__device__ __forceinline__ void store_h_tile(char* smem, int tileoff, int row, int j, float h) {
    __nv_bfloat16 hh = __float2bfloat16(h);
    __nv_bfloat16 hl = __float2bfloat16(h - __bfloat162float(hh));
    *(__nv_bfloat16*)(smem + tileoff + row * HPB + j * 2)       = hh;
    *(__nv_bfloat16*)(smem + tileoff + row * HPB + 128 + j * 2) = hl;
}

// Layer-1 epilogue: writes h1 into tile h1off (no barrier needed: different buffer)
__device__ __forceinline__ void epi_l1(
    float acc[2][5][4], int cnt, int nt0, int lane, int jpar, const int* rows,
    const float4* b1q, const float4* wxq, const float* xv,
    float c1[2][5], char* smem, int h1off)
{
    #pragma unroll
    for (int mt = 0; mt < 2; ++mt) {
        #pragma unroll
        for (int nti = 0; nti < 5; ++nti) if (nti < cnt) {
            float gi_, gf, gg, go;
            regroup(acc[mt][nti], lane, gi_, gf, gg, go);
            int j = 2 * (nt0 + nti) + jpar;
            float4 b  = b1q[j];
            float4 wx = wxq[j];
            float pi = fmaf(xv[mt], wx.x, gi_ + b.x);
            float pf = fmaf(xv[mt], wx.y, gf + b.y);
            float pg = fmaf(xv[mt], wx.z, gg + b.z);
            float po = fmaf(xv[mt], wx.w, go + b.w);
            float cn = fmaf(sigm(pf), c1[mt][nti], sigm(pi) * tanh_fast(pg));
            c1[mt][nti] = cn;
            float h = sigm(po) * tanh_fast(cn);
            if (j < NS) store_h_tile(smem, h1off, rows[mt], j, h);
        }
    }
}

// Layer-2 epilogue: writes h2 (in place) + y partials
__device__ __forceinline__ void epi_l2(
    float acc[2][5][4], int cnt, int nt0, int lane, int jpar, const int* rows,
    const float4* b2q, const float* wls,
    float c2[2][5], char* smem, float* yw, int ng)
{
    #pragma unroll
    for (int mt = 0; mt < 2; ++mt) {
        float yp = 0.0f;
        #pragma unroll
        for (int nti = 0; nti < 5; ++nti) if (nti < cnt) {
            float gi_, gf, gg, go;
            regroup(acc[mt][nti], lane, gi_, gf, gg, go);
            int j = 2 * (nt0 + nti) + jpar;
            float4 b = b2q[j];
            float pi = gi_ + b.x, pf = gf + b.y, pg = gg + b.z, po = go + b.w;
            float cn = fmaf(sigm(pf), c2[mt][nti], sigm(pi) * tanh_fast(pg));
            c2[mt][nti] = cn;
            float h = sigm(po) * tanh_fast(cn);
            if (j < NS) {
                store_h_tile(smem, OFF_H2, rows[mt], j, h);
                yp = fmaf(wls[j], h, yp);
            }
        }
        float ys = yp + __shfl_xor_sync(0xFFFFFFFFu, yp, 2);
        if (!(lane & 2)) yw[rows[mt] * 8 + ng] = ys;
    }
}

__global__ __launch_bounds__(NTHREADS, 1)
void lstm2_hmma13_kernel(
    const float* __restrict__ x,      // [B, T]
    const float* __restrict__ Wih1,   // [204, 1]
    const float* __restrict__ Whh1,   // [204, 51]
    const float* __restrict__ bih1,
    const float* __restrict__ bhh1,
    const float* __restrict__ Wih2,   // [204, 51]
    const float* __restrict__ Whh2,   // [204, 51]
    const float* __restrict__ bih2,
    const float* __restrict__ bhh2,
    const float* __restrict__ Wlin,   // [1, 51]
    const float* __restrict__ blin,
    float* __restrict__ out)          // [B, T]
{
    extern __shared__ char smem[];
    const u32 sb = smem_u32(smem);
    const int tid  = threadIdx.x;
    const int wid  = tid >> 5;
    const int lane = tid & 31;
    const int mg   = wid / 6;                 // m-group 0/1 (rows 0-31 / 32-63)
    const int ng   = wid % 6;                 // n-group
    const int cnt  = (ng < 2) ? 5 : 4;
    const int nt0  = (ng < 2) ? 5 * ng : 10 + 4 * (ng - 2);
    const int rb   = blockIdx.x * M_ROWS;

    for (int i = tid; i < SMEM_TOTAL / 4; i += NTHREADS) ((u32*)smem)[i] = 0;
    __syncthreads();

    float4* b1q = (float4*)(smem + OFF_B1Q);
    float4* b2q = (float4*)(smem + OFF_B2Q);
    float4* wxq = (float4*)(smem + OFF_WXQ);
    float*  wls = (float*)(smem + OFF_WLS);
    float*  yw  = (float*)(smem + OFF_YW);

    // ---- stage weights: B row n = 4*j + gi, hi/lo bf16 split ----
    for (int idx = tid; idx < 208 * NS; idx += NTHREADS) {
        int n = idx / NS, m = idx % NS;
        int j = n >> 2, gi = n & 3;
        if (j < NS) {
            int g = gi * NS + j;
            float w1  = Whh1[g * NS + m];
            float wi2 = Wih2[g * NS + m];
            float wh2 = Whh2[g * NS + m];
            __nv_bfloat16 h, l;
            h = __float2bfloat16(w1);  l = __float2bfloat16(w1 - __bfloat162float(h));
            *(__nv_bfloat16*)(smem + OFF_B1 + n * B1P + m * 2)        = h;
            *(__nv_bfloat16*)(smem + OFF_B1 + n * B1P + (64 + m) * 2) = l;
            h = __float2bfloat16(wi2); l = __float2bfloat16(wi2 - __bfloat162float(h));
            *(__nv_bfloat16*)(smem + OFF_B2 + n * B2P + m * 2)        = h;
            *(__nv_bfloat16*)(smem + OFF_B2 + n * B2P + (64 + m) * 2) = l;
            h = __float2bfloat16(wh2); l = __float2bfloat16(wh2 - __bfloat162float(h));
            *(__nv_bfloat16*)(smem + OFF_B2 + n * B2P + (128 + m) * 2) = h;
            *(__nv_bfloat16*)(smem + OFF_B2 + n * B2P + (192 + m) * 2) = l;
        }
    }
    for (int j = tid; j < NS; j += NTHREADS) {
        b1q[j] = make_float4(bih1[j] + bhh1[j], bih1[j + NS] + bhh1[j + NS],
                             bih1[j + 2 * NS] + bhh1[j + 2 * NS], bih1[j + 3 * NS] + bhh1[j + 3 * NS]);
        b2q[j] = make_float4(bih2[j] + bhh2[j], bih2[j + NS] + bhh2[j + NS],
                             bih2[j + 2 * NS] + bhh2[j + 2 * NS], bih2[j + 3 * NS] + bhh2[j + 3 * NS]);
        wxq[j] = make_float4(Wih1[j], Wih1[j + NS], Wih1[j + 2 * NS], Wih1[j + 3 * NS]);
        wls[j] = Wlin[j];
    }
    __syncthreads();

    const float blin_v = blin[0];
    const int m0base = 32 * mg;
    const int rbase  = m0base + (lane >> 2) + 8 * (lane & 1);
    const int rows[2] = {rbase, rbase + 16};
    const int jpar = (lane >> 1) & 1;
    const u32 sbB1 = sb + OFF_B1;
    const u32 sbB2 = sb + OFF_B2;
    const u32 h2t  = sb + OFF_H2;

    float c1[2][5], c2[2][5];
    #pragma unroll
    for (int mt = 0; mt < 2; ++mt)
        #pragma unroll
        for (int i = 0; i < 5; ++i) { c1[mt][i] = 0.0f; c2[mt][i] = 0.0f; }

    // ---- prologue: h1(0) = L1(x(0), h=0, c=0) into tile H1_0 ----
    {
        float acc0[2][5][4];
        #pragma unroll
        for (int mt = 0; mt < 2; ++mt)
            #pragma unroll
            for (int i = 0; i < 5; ++i)
                #pragma unroll
                for (int q = 0; q < 4; ++q) acc0[mt][i][q] = 0.0f;
        float xv0[2];
        #pragma unroll
        for (int mt = 0; mt < 2; ++mt)
            xv0[mt] = __ldg(&x[(size_t)(rb + rows[mt]) * T_LEN]);
        epi_l1(acc0, cnt, nt0, lane, jpar, rows, b1q, wxq, xv0, c1, smem, OFF_H1_0);
    }
    __syncthreads();

    // ---- main loop: step t uses {h1(t) in buf t&1, h2(t-1) in H2} ----
    for (int t = 0; t < T_LEN; ++t) {
        const u32 h1cur   = sb + ((t & 1) ? OFF_H1_1 : OFF_H1_0);
        const int h1nxtOf = (t & 1) ? OFF_H1_0 : OFF_H1_1;

        // y(t-1) store, overlapped with MMA phase (yw stable until post-bar epi_l2)
        if (tid < M_ROWS && t > 0) {
            float acc = blin_v;
            #pragma unroll
            for (int g2 = 0; g2 < 6; ++g2) acc += yw[tid * 8 + g2];
            out[(size_t)(rb + tid) * T_LEN + (t - 1)] = acc;
        }

        float xv[2];
        #pragma unroll
        for (int mt = 0; mt < 2; ++mt)
            xv[mt] = (t + 1 < T_LEN)
                   ? __ldg(&x[(size_t)(rb + rows[mt]) * T_LEN + t + 1]) : 0.0f;

        // ================= Phase 1: acc1 = h1(t) * W1, then epi_l1 =================
        {
            float acc1[2][5][4];
            #pragma unroll
            for (int mt = 0; mt < 2; ++mt)
                #pragma unroll
                for (int i = 0; i < 5; ++i)
                    #pragma unroll
                    for (int q = 0; q < 4; ++q) acc1[mt][i][q] = 0.0f;

            #pragma unroll
            for (int half = 0; half < 2; ++half) {
                u32 ahi[2][2][4], alo[2][2][4];
                #pragma unroll
                for (int mt = 0; mt < 2; ++mt)
                    #pragma unroll
                    for (int kk = 0; kk < 2; ++kk) {
                        ldsm4(ahi[mt][kk], a_addr(h1cur, m0base + 16 * mt, 2 * half + kk, lane));
                        ldsm4(alo[mt][kk], a_addr(h1cur, m0base + 16 * mt, 4 + 2 * half + kk, lane));
                    }
                #pragma unroll
                for (int nti = 0; nti < 5; ++nti) if (nti < cnt) {
                    int nt = nt0 + nti;
                    u32 bh[4], bl[4];
                    ldsm4(bh, b_addr(sbB1, B1P, nt, 2 * half, lane));
                    ldsm4(bl, b_addr(sbB1, B1P, nt, 4 + 2 * half, lane));
                    #pragma unroll
                    for (int mt = 0; mt < 2; ++mt)
                        #pragma unroll
                        for (int kk = 0; kk < 2; ++kk) {
                            mma_bf16(acc1[mt][nti], ahi[mt][kk], bh + 2 * kk);
                            mma_bf16(acc1[mt][nti], alo[mt][kk], bh + 2 * kk);
                            mma_bf16(acc1[mt][nti], ahi[mt][kk], bl + 2 * kk);
                        }
                }
            }
            // epi_l1 needs no barrier: writes h1nxt (other buffer), disjoint (row,j)
            epi_l1(acc1, cnt, nt0, lane, jpar, rows, b1q, wxq, xv, c1, smem, h1nxtOf);
        }   // acc1 dead here — register pressure released

        // ================= Phase 2: acc2 = h1(t)*Wi2 + h2(t-1)*Wh2 =================
        {
            float acc2[2][5][4];
            #pragma unroll
            for (int mt = 0; mt < 2; ++mt)
                #pragma unroll
                for (int i = 0; i < 5; ++i)
                    #pragma unroll
                    for (int q = 0; q < 4; ++q) acc2[mt][i][q] = 0.0f;

            // P2: h1 * Wi2
            #pragma unroll
            for (int half = 0; half < 2; ++half) {
                u32 ahi[2][2][4], alo[2][2][4];
                #pragma unroll
                for (int mt = 0; mt < 2; ++mt)
                    #pragma unroll
                    for (int kk = 0; kk < 2; ++kk) {
                        ldsm4(ahi[mt][kk], a_addr(h1cur, m0base + 16 * mt, 2 * half + kk, lane));
                        ldsm4(alo[mt][kk], a_addr(h1cur, m0base + 16 * mt, 4 + 2 * half + kk, lane));
                    }
                #pragma unroll
                for (int nti = 0; nti < 5; ++nti) if (nti < cnt) {
                    int nt = nt0 + nti;
                    u32 bh[4], bl[4];
                    ldsm4(bh, b_addr(sbB2, B2P, nt, 2 * half, lane));
                    ldsm4(bl, b_addr(sbB2, B2P, nt, 4 + 2 * half, lane));
                    #pragma unroll
                    for (int mt = 0; mt < 2; ++mt)
                        #pragma unroll
                        for (int kk = 0; kk < 2; ++kk) {
                            mma_bf16(acc2[mt][nti], ahi[mt][kk], bh + 2 * kk);
                            mma_bf16(acc2[mt][nti], alo[mt][kk], bh + 2 * kk);
                            mma_bf16(acc2[mt][nti], ahi[mt][kk], bl + 2 * kk);
                        }
                }
            }
            // P3: h2 * Wh2
            #pragma unroll
            for (int half = 0; half < 2; ++half) {
                u32 ahi[2][2][4], alo[2][2][4];
                #pragma unroll
                for (int mt = 0; mt < 2; ++mt)
                    #pragma unroll
                    for (int kk = 0; kk < 2; ++kk) {
                        ldsm4(ahi[mt][kk], a_addr(h2t, m0base + 16 * mt, 2 * half + kk, lane));
                        ldsm4(alo[mt][kk], a_addr(h2t, m0base + 16 * mt, 4 + 2 * half + kk, lane));
                    }
                #pragma unroll
                for (int nti = 0; nti < 5; ++nti) if (nti < cnt) {
                    int nt = nt0 + nti;
                    u32 bh[4], bl[4];
                    ldsm4(bh, b_addr(sbB2, B2P, nt, 8 + 2 * half, lane));
                    ldsm4(bl, b_addr(sbB2, B2P, nt, 12 + 2 * half, lane));
                    #pragma unroll
                    for (int mt = 0; mt < 2; ++mt)
                        #pragma unroll
                        for (int kk = 0; kk < 2; ++kk) {
                            mma_bf16(acc2[mt][nti], ahi[mt][kk], bh + 2 * kk);
                            mma_bf16(acc2[mt][nti], alo[mt][kk], bh + 2 * kk);
                            mma_bf16(acc2[mt][nti], ahi[mt][kk], bl + 2 * kk);
                        }
                }
            }

            __syncthreads();   // all warps' h2 reads (and yw reads) complete

            epi_l2(acc2, cnt, nt0, lane, jpar, rows, b2q, wls, c2, smem, yw, ng);
        }

        __syncthreads();   // h1(t+1), h2(t), yw(t) visible
    }

    // ---- final projection: y(T-1) ----
    if (tid < M_ROWS) {
        float acc = blin_v;
        #pragma unroll
        for (int g2 = 0; g2 < 6; ++g2) acc += yw[tid * 8 + g2];
        out[(size_t)(rb + tid) * T_LEN + (T_LEN - 1)] = acc;
    }
}

extern "C" void kernel_launch(void* const* d_in, const int* in_sizes, int n_in,
                              void* d_out, int out_size) {
    const float* x    = (const float*)d_in[0];
    const float* Wih1 = (const float*)d_in[1];
    const float* Whh1 = (const float*)d_in[2];
    const float* bih1 = (const float*)d_in[3];
    const float* bhh1 = (const float*)d_in[4];
    const float* Wih2 = (const float*)d_in[5];
    const float* Whh2 = (const float*)d_in[6];
    const float* bih2 = (const float*)d_in[7];
    const float* bhh2 = (const float*)d_in[8];
    const float* Wlin = (const float*)d_in[9];
    const float* blin = (const float*)d_in[10];
    float* out = (float*)d_out;

    cudaFuncSetAttribute(lstm2_hmma13_kernel,
                         cudaFuncAttributeMaxDynamicSharedMemorySize, SMEM_TOTAL);

    dim3 grid(NCTA);          // 128 CTAs x 64 rows
    dim3 block(NTHREADS);     // 384 threads = 12 warps
    lstm2_hmma13_kernel<<<grid, block, SMEM_TOTAL>>>(
        x, Wih1, Whh1, bih1, bhh1, Wih2, Whh2, bih2, bhh2, Wlin, blin, out);
}

// round 14
// speedup vs baseline: 3.0470x; 1.8796x over previous
#include <cuda_runtime.h>
#include <cuda_bf16.h>
#include <cstdint>

// ---------------- fixed shapes ----------------
#define NS      51
#define T_LEN   2048
#define B_TOT   8192
#define M_ROWS  64
#define NCTA    (B_TOT / M_ROWS)      // 128
#define NTHREADS 384                  // 12 warps = 2 m-groups x 6 n-groups

// SMEM layout (bytes)
#define HPB     272                   // h tile pitch: 128 bf16 (hi|lo) + pad
#define HTSZ    (64 * HPB)            // 17408 per h tile
#define B1P     272                   // B1: [208 n][128 bf16] (W1hi|W1lo)
#define B2P     528                   // B2: [208 n][256 bf16] (Wi2hi|Wi2lo|Wh2hi|Wh2lo)

#define OFF_H1_0 0
#define OFF_H1_1 HTSZ                 // 17408
#define OFF_H2   (2 * HTSZ)           // 34816
#define OFF_B1   (3 * HTSZ)           // 52224
#define OFF_B2   (OFF_B1 + 208 * B1P) // 108800
#define OFF_B1Q  (OFF_B2 + 208 * B2P) // 218624
#define OFF_B2Q  (OFF_B1Q + 832)
#define OFF_WXQ  (OFF_B2Q + 832)
#define OFF_WLS  (OFF_WXQ + 832)      // float[52] + pad
#define OFF_YW   (OFF_WLS + 224)      // float[64][8]
#define SMEM_TOTAL (OFF_YW + 64 * 8 * 4)   // 223392

typedef uint32_t u32;

// ---------------- helpers (fragment maps verified in R9) ----------------
__device__ __forceinline__ u32 smem_u32(const void* p) {
    u32 a;
    asm("{ .reg .u64 t; cvta.to.shared.u64 t, %1; cvt.u32.u64 %0, t; }" : "=r"(a) : "l"(p));
    return a;
}
__device__ __forceinline__ void ldsm4(u32* r, u32 addr) {
    asm volatile("ldmatrix.sync.aligned.m8n8.x4.shared.b16 {%0,%1,%2,%3}, [%4];"
                 : "=r"(r[0]), "=r"(r[1]), "=r"(r[2]), "=r"(r[3]) : "r"(addr));
}
__device__ __forceinline__ void mma_bf16(float* c, const u32* a, const u32* b) {
    asm volatile("mma.sync.aligned.m16n8k16.row.col.f32.bf16.bf16.f32 "
                 "{%0,%1,%2,%3}, {%4,%5,%6,%7}, {%8,%9}, {%0,%1,%2,%3};"
                 : "+f"(c[0]), "+f"(c[1]), "+f"(c[2]), "+f"(c[3])
                 : "r"(a[0]), "r"(a[1]), "r"(a[2]), "r"(a[3]), "r"(b[0]), "r"(b[1]));
}
// Single-MUFU activations (sm_75+ tanh unit)
__device__ __forceinline__ float tanh_hw(float v) {
    float r; asm("tanh.approx.f32 %0, %1;" : "=f"(r) : "f"(v)); return r;
}
__device__ __forceinline__ float sigm(float v) {
    return fmaf(0.5f, tanh_hw(0.5f * v), 0.5f);
}

// A-fragment (m16k16) in an h tile (pitch HPB); kchunk 0-3 = hi, 4-7 = lo
__device__ __forceinline__ u32 a_addr(u32 tile, int m0, int kchunk, int lane) {
    int r  = m0 + (lane & 15);
    int cb = kchunk * 32 + ((lane >> 4) << 4);
    return tile + r * HPB + cb;
}
// B-fragment x4 (one n8 tile, two k16 tiles starting at kchunk)
__device__ __forceinline__ u32 b_addr(u32 sbB, int pitch, int nt, int kchunk, int lane) {
    int n  = nt * 8 + (lane & 7);
    int cb = kchunk * 32 + ((lane >> 3) << 4);
    return sbB + n * pitch + cb;
}

// Regroup D-frag gates (verified): lane ends owning (i,f,g,o) of ONE (row,unit)
__device__ __forceinline__ void regroup(const float* C, int lane,
                                        float& gi_, float& gf, float& gg, float& go) {
    float v  = (lane & 1) ? C[0] : C[2];
    float sv = __shfl_xor_sync(0xFFFFFFFFu, v, 1);
    float w  = (lane & 1) ? C[1] : C[3];
    float sw = __shfl_xor_sync(0xFFFFFFFFu, w, 1);
    if (lane & 1) { gi_ = sv;   gf = sw;   gg = C[2]; go = C[3]; }
    else          { gi_ = C[0]; gf = C[1]; gg = sv;   go = sw;  }
}

__device__ __forceinline__ void store_h_tile(char* smem, int tileoff, int row, int j, float h) {
    __nv_bfloat16 hh = __float2bfloat16(h);
    __nv_bfloat16 hl = __float2bfloat16(h - __bfloat162float(hh));
    *(__nv_bfloat16*)(smem + tileoff + row * HPB + j * 2)       = hh;
    *(__nv_bfloat16*)(smem + tileoff + row * HPB + 128 + j * 2) = hl;
}

// Layer-1 epilogue: writes h1 into tile h1off (no barrier needed: other buffer)
__device__ __forceinline__ void epi_l1(
    float acc[2][5][4], int cnt, int nt0, int lane, int jpar, const int* rows,
    const float4* b1q, const float4* wxq, const float* xv,
    float c1[2][5], char* smem, int h1off)
{
    #pragma unroll
    for (int mt = 0; mt < 2; ++mt) {
        #pragma unroll
        for (int nti = 0; nti < 5; ++nti) if (nti < cnt) {
            float gi_, gf, gg, go;
            regroup(acc[mt][nti], lane, gi_, gf, gg, go);
            int j = 2 * (nt0 + nti) + jpar;
            float4 b  = b1q[j];
            float4 wx = wxq[j];
            float pi = fmaf(xv[mt], wx.x, gi_ + b.x);
            float pf = fmaf(xv[mt], wx.y, gf + b.y);
            float pg = fmaf(xv[mt], wx.z, gg + b.z);
            float po = fmaf(xv[mt], wx.w, go + b.w);
            float cn = fmaf(sigm(pf), c1[mt][nti], sigm(pi) * tanh_hw(pg));
            c1[mt][nti] = cn;
            float h = sigm(po) * tanh_hw(cn);
            if (j < NS) store_h_tile(smem, h1off, rows[mt], j, h);
        }
    }
}

// Layer-2 epilogue: writes h2 (in place) + y partials
__device__ __forceinline__ void epi_l2(
    float acc[2][5][4], int cnt, int nt0, int lane, int jpar, const int* rows,
    const float4* b2q, const float* wls,
    float c2[2][5], char* smem, float* yw, int ng)
{
    #pragma unroll
    for (int mt = 0; mt < 2; ++mt) {
        float yp = 0.0f;
        #pragma unroll
        for (int nti = 0; nti < 5; ++nti) if (nti < cnt) {
            float gi_, gf, gg, go;
            regroup(acc[mt][nti], lane, gi_, gf, gg, go);
            int j = 2 * (nt0 + nti) + jpar;
            float4 b = b2q[j];
            float pi = gi_ + b.x, pf = gf + b.y, pg = gg + b.z, po = go + b.w;
            float cn = fmaf(sigm(pf), c2[mt][nti], sigm(pi) * tanh_hw(pg));
            c2[mt][nti] = cn;
            float h = sigm(po) * tanh_hw(cn);
            if (j < NS) {
                store_h_tile(smem, OFF_H2, rows[mt], j, h);
                yp = fmaf(wls[j], h, yp);
            }
        }
        float ys = yp + __shfl_xor_sync(0xFFFFFFFFu, yp, 2);
        if (!(lane & 2)) yw[rows[mt] * 8 + ng] = ys;
    }
}

__global__ __launch_bounds__(NTHREADS, 1)
void lstm2_hmma14_kernel(
    const float* __restrict__ x,      // [B, T]
    const float* __restrict__ Wih1,   // [204, 1]
    const float* __restrict__ Whh1,   // [204, 51]
    const float* __restrict__ bih1,
    const float* __restrict__ bhh1,
    const float* __restrict__ Wih2,   // [204, 51]
    const float* __restrict__ Whh2,   // [204, 51]
    const float* __restrict__ bih2,
    const float* __restrict__ bhh2,
    const float* __restrict__ Wlin,   // [1, 51]
    const float* __restrict__ blin,
    float* __restrict__ out)          // [B, T]
{
    extern __shared__ char smem[];
    const u32 sb = smem_u32(smem);
    const int tid  = threadIdx.x;
    const int wid  = tid >> 5;
    const int lane = tid & 31;
    const int mg   = wid / 6;                 // m-group 0/1 (rows 0-31 / 32-63)
    const int ng   = wid % 6;                 // n-group
    const int cnt  = (ng < 2) ? 5 : 4;
    const int nt0  = (ng < 2) ? 5 * ng : 10 + 4 * (ng - 2);
    const int rb   = blockIdx.x * M_ROWS;
    const int gtid = tid - 192 * mg;          // tid within my m-group (0..191)
    const int barid = mg + 1;

    for (int i = tid; i < SMEM_TOTAL / 4; i += NTHREADS) ((u32*)smem)[i] = 0;
    __syncthreads();

    float4* b1q = (float4*)(smem + OFF_B1Q);
    float4* b2q = (float4*)(smem + OFF_B2Q);
    float4* wxq = (float4*)(smem + OFF_WXQ);
    float*  wls = (float*)(smem + OFF_WLS);
    float*  yw  = (float*)(smem + OFF_YW);

    // ---- stage weights: B row n = 4*j + gi, hi/lo bf16 split ----
    for (int idx = tid; idx < 208 * NS; idx += NTHREADS) {
        int n = idx / NS, m = idx % NS;
        int j = n >> 2, gi = n & 3;
        if (j < NS) {
            int g = gi * NS + j;
            float w1  = Whh1[g * NS + m];
            float wi2 = Wih2[g * NS + m];
            float wh2 = Whh2[g * NS + m];
            __nv_bfloat16 h, l;
            h = __float2bfloat16(w1);  l = __float2bfloat16(w1 - __bfloat162float(h));
            *(__nv_bfloat16*)(smem + OFF_B1 + n * B1P + m * 2)        = h;
            *(__nv_bfloat16*)(smem + OFF_B1 + n * B1P + (64 + m) * 2) = l;
            h = __float2bfloat16(wi2); l = __float2bfloat16(wi2 - __bfloat162float(h));
            *(__nv_bfloat16*)(smem + OFF_B2 + n * B2P + m * 2)        = h;
            *(__nv_bfloat16*)(smem + OFF_B2 + n * B2P + (64 + m) * 2) = l;
            h = __float2bfloat16(wh2); l = __float2bfloat16(wh2 - __bfloat162float(h));
            *(__nv_bfloat16*)(smem + OFF_B2 + n * B2P + (128 + m) * 2) = h;
            *(__nv_bfloat16*)(smem + OFF_B2 + n * B2P + (192 + m) * 2) = l;
        }
    }
    for (int j = tid; j < NS; j += NTHREADS) {
        b1q[j] = make_float4(bih1[j] + bhh1[j], bih1[j + NS] + bhh1[j + NS],
                             bih1[j + 2 * NS] + bhh1[j + 2 * NS], bih1[j + 3 * NS] + bhh1[j + 3 * NS]);
        b2q[j] = make_float4(bih2[j] + bhh2[j], bih2[j + NS] + bhh2[j + NS],
                             bih2[j + 2 * NS] + bhh2[j + 2 * NS], bih2[j + 3 * NS] + bhh2[j + 3 * NS]);
        wxq[j] = make_float4(Wih1[j], Wih1[j + NS], Wih1[j + 2 * NS], Wih1[j + 3 * NS]);
        wls[j] = Wlin[j];
    }
    __syncthreads();

    const float blin_v = blin[0];
    const int m0base = 32 * mg;
    const int rbase  = m0base + (lane >> 2) + 8 * (lane & 1);
    const int rows[2] = {rbase, rbase + 16};
    const int jpar = (lane >> 1) & 1;
    const u32 sbB1 = sb + OFF_B1;
    const u32 sbB2 = sb + OFF_B2;
    const u32 h2t  = sb + OFF_H2;

    float c1[2][5], c2[2][5];
    #pragma unroll
    for (int mt = 0; mt < 2; ++mt)
        #pragma unroll
        for (int i = 0; i < 5; ++i) { c1[mt][i] = 0.0f; c2[mt][i] = 0.0f; }

    // ---- prologue: h1(0) = L1(x(0), h=0, c=0) into tile H1_0 ----
    {
        float acc0[2][5][4];
        #pragma unroll
        for (int mt = 0; mt < 2; ++mt)
            #pragma unroll
            for (int i = 0; i < 5; ++i)
                #pragma unroll
                for (int q = 0; q < 4; ++q) acc0[mt][i][q] = 0.0f;
        float xv0[2];
        #pragma unroll
        for (int mt = 0; mt < 2; ++mt)
            xv0[mt] = __ldg(&x[(size_t)(rb + rows[mt]) * T_LEN]);
        epi_l1(acc0, cnt, nt0, lane, jpar, rows, b1q, wxq, xv0, c1, smem, OFF_H1_0);
    }
    __syncthreads();

    // ---- main loop: all inter-step deps are m-group-private -> group barriers ----
    for (int t = 0; t < T_LEN; ++t) {
        const u32 h1cur   = sb + ((t & 1) ? OFF_H1_1 : OFF_H1_0);
        const int h1nxtOf = (t & 1) ? OFF_H1_0 : OFF_H1_1;

        // y(t-1) store (group-local rows), overlapped with MMA phase
        if (gtid < 32 && t > 0) {
            int r = m0base + gtid;
            float acc = blin_v;
            #pragma unroll
            for (int g2 = 0; g2 < 6; ++g2) acc += yw[r * 8 + g2];
            out[(size_t)(rb + r) * T_LEN + (t - 1)] = acc;
        }

        float xv[2];
        #pragma unroll
        for (int mt = 0; mt < 2; ++mt)
            xv[mt] = (t + 1 < T_LEN)
                   ? __ldg(&x[(size_t)(rb + rows[mt]) * T_LEN + t + 1]) : 0.0f;

        // ================= Phase 1: acc1 = h1(t) * W1, then epi_l1 =================
        {
            float acc1[2][5][4];
            #pragma unroll
            for (int mt = 0; mt < 2; ++mt)
                #pragma unroll
                for (int i = 0; i < 5; ++i)
                    #pragma unroll
                    for (int q = 0; q < 4; ++q) acc1[mt][i][q] = 0.0f;

            #pragma unroll
            for (int half = 0; half < 2; ++half) {
                u32 ahi[2][2][4], alo[2][2][4];
                #pragma unroll
                for (int mt = 0; mt < 2; ++mt)
                    #pragma unroll
                    for (int kk = 0; kk < 2; ++kk) {
                        ldsm4(ahi[mt][kk], a_addr(h1cur, m0base + 16 * mt, 2 * half + kk, lane));
                        ldsm4(alo[mt][kk], a_addr(h1cur, m0base + 16 * mt, 4 + 2 * half + kk, lane));
                    }
                #pragma unroll
                for (int nti = 0; nti < 5; ++nti) if (nti < cnt) {
                    int nt = nt0 + nti;
                    u32 bh[4], bl[4];
                    ldsm4(bh, b_addr(sbB1, B1P, nt, 2 * half, lane));
                    ldsm4(bl, b_addr(sbB1, B1P, nt, 4 + 2 * half, lane));
                    #pragma unroll
                    for (int mt = 0; mt < 2; ++mt)
                        #pragma unroll
                        for (int kk = 0; kk < 2; ++kk) {
                            mma_bf16(acc1[mt][nti], ahi[mt][kk], bh + 2 * kk);
                            mma_bf16(acc1[mt][nti], alo[mt][kk], bh + 2 * kk);
                            mma_bf16(acc1[mt][nti], ahi[mt][kk], bl + 2 * kk);
                        }
                }
            }
            epi_l1(acc1, cnt, nt0, lane, jpar, rows, b1q, wxq, xv, c1, smem, h1nxtOf);
        }   // acc1 dead — register pressure released

        // ================= Phase 2: acc2 = h1(t)*Wi2 + h2(t-1)*Wh2 =================
        {
            float acc2[2][5][4];
            #pragma unroll
            for (int mt = 0; mt < 2; ++mt)
                #pragma unroll
                for (int i = 0; i < 5; ++i)
                    #pragma unroll
                    for (int q = 0; q < 4; ++q) acc2[mt][i][q] = 0.0f;

            // P2: h1 * Wi2
            #pragma unroll
            for (int half = 0; half < 2; ++half) {
                u32 ahi[2][2][4], alo[2][2][4];
                #pragma unroll
                for (int mt = 0; mt < 2; ++mt)
                    #pragma unroll
                    for (int kk = 0; kk < 2; ++kk) {
                        ldsm4(ahi[mt][kk], a_addr(h1cur, m0base + 16 * mt, 2 * half + kk, lane));
                        ldsm4(alo[mt][kk], a_addr(h1cur, m0base + 16 * mt, 4 + 2 * half + kk, lane));
                    }
                #pragma unroll
                for (int nti = 0; nti < 5; ++nti) if (nti < cnt) {
                    int nt = nt0 + nti;
                    u32 bh[4], bl[4];
                    ldsm4(bh, b_addr(sbB2, B2P, nt, 2 * half, lane));
                    ldsm4(bl, b_addr(sbB2, B2P, nt, 4 + 2 * half, lane));
                    #pragma unroll
                    for (int mt = 0; mt < 2; ++mt)
                        #pragma unroll
                        for (int kk = 0; kk < 2; ++kk) {
                            mma_bf16(acc2[mt][nti], ahi[mt][kk], bh + 2 * kk);
                            mma_bf16(acc2[mt][nti], alo[mt][kk], bh + 2 * kk);
                            mma_bf16(acc2[mt][nti], ahi[mt][kk], bl + 2 * kk);
                        }
                }
            }
            // P3: h2 * Wh2
            #pragma unroll
            for (int half = 0; half < 2; ++half) {
                u32 ahi[2][2][4], alo[2][2][4];
                #pragma unroll
                for (int mt = 0; mt < 2; ++mt)
                    #pragma unroll
                    for (int kk = 0; kk < 2; ++kk) {
                        ldsm4(ahi[mt][kk], a_addr(h2t, m0base + 16 * mt, 2 * half + kk, lane));
                        ldsm4(alo[mt][kk], a_addr(h2t, m0base + 16 * mt, 4 + 2 * half + kk, lane));
                    }
                #pragma unroll
                for (int nti = 0; nti < 5; ++nti) if (nti < cnt) {
                    int nt = nt0 + nti;
                    u32 bh[4], bl[4];
                    ldsm4(bh, b_addr(sbB2, B2P, nt, 8 + 2 * half, lane));
                    ldsm4(bl, b_addr(sbB2, B2P, nt, 12 + 2 * half, lane));
                    #pragma unroll
                    for (int mt = 0; mt < 2; ++mt)
                        #pragma unroll
                        for (int kk = 0; kk < 2; ++kk) {
                            mma_bf16(acc2[mt][nti], ahi[mt][kk], bh + 2 * kk);
                            mma_bf16(acc2[mt][nti], alo[mt][kk], bh + 2 * kk);
                            mma_bf16(acc2[mt][nti], ahi[mt][kk], bl + 2 * kk);
                        }
                }
            }

            // group barrier: my group's h2 reads (and yw reads) complete
            asm volatile("bar.sync %0, 192;" :: "r"(barid) : "memory");

            epi_l2(acc2, cnt, nt0, lane, jpar, rows, b2q, wls, c2, smem, yw, ng);
        }

        // group barrier: my group's h1(t+1), h2(t), yw(t) writes visible
        asm volatile("bar.sync %0, 192;" :: "r"(barid) : "memory");
    }

    // ---- final projection: y(T-1), group-local rows ----
    if (gtid < 32) {
        int r = m0base + gtid;
        float acc = blin_v;
        #pragma unroll
        for (int g2 = 0; g2 < 6; ++g2) acc += yw[r * 8 + g2];
        out[(size_t)(rb + r) * T_LEN + (T_LEN - 1)] = acc;
    }
}

extern "C" void kernel_launch(void* const* d_in, const int* in_sizes, int n_in,
                              void* d_out, int out_size) {
    const float* x    = (const float*)d_in[0];
    const float* Wih1 = (const float*)d_in[1];
    const float* Whh1 = (const float*)d_in[2];
    const float* bih1 = (const float*)d_in[3];
    const float* bhh1 = (const float*)d_in[4];
    const float* Wih2 = (const float*)d_in[5];
    const float* Whh2 = (const float*)d_in[6];
    const float* bih2 = (const float*)d_in[7];
    const float* bhh2 = (const float*)d_in[8];
    const float* Wlin = (const float*)d_in[9];
    const float* blin = (const float*)d_in[10];
    float* out = (float*)d_out;

    cudaFuncSetAttribute(lstm2_hmma14_kernel,
                         cudaFuncAttributeMaxDynamicSharedMemorySize, SMEM_TOTAL);

    dim3 grid(NCTA);          // 128 CTAs x 64 rows
    dim3 block(NTHREADS);     // 384 threads = 12 warps
    lstm2_hmma14_kernel<<<grid, block, SMEM_TOTAL>>>(
        x, Wih1, Whh1, bih1, bhh1, Wih2, Whh2, bih2, bhh2, Wlin, blin, out);
}

// round 15
// speedup vs baseline: 3.8406x; 1.2604x over previous
#include <cuda_runtime.h>
#include <cuda_fp16.h>
#include <cstdint>

// ---------------- fixed shapes ----------------
#define NS      51
#define T_LEN   2048
#define B_TOT   8192
#define M_ROWS  64
#define NCTA    (B_TOT / M_ROWS)      // 128
#define NTHREADS 384                  // 12 warps = 2 m-groups x 6 n-groups

// SMEM layout (bytes)
#define HPB     272                   // h tile pitch: 128 fp16 (hi|lo) + pad
#define HTSZ    (64 * HPB)            // 17408 per h tile
#define B1P     144                   // B1: [208 n][64 fp16]  (W1, fp16)
#define B2P     272                   // B2: [208 n][128 fp16] (Wi2|Wh2, fp16)

#define OFF_H1_0 0
#define OFF_H1_1 HTSZ                 // 17408
#define OFF_H2   (2 * HTSZ)           // 34816
#define OFF_B1   (3 * HTSZ)           // 52224
#define OFF_B2   (OFF_B1 + 208 * B1P) // 82176
#define OFF_B1Q  (OFF_B2 + 208 * B2P) // 138752
#define OFF_B2Q  (OFF_B1Q + 832)
#define OFF_WXQ  (OFF_B2Q + 832)
#define OFF_WLS  (OFF_WXQ + 832)      // float[52] + pad
#define OFF_YW   (OFF_WLS + 224)      // float[64][8]
#define SMEM_TOTAL (OFF_YW + 64 * 8 * 4)   // 143920

typedef uint32_t u32;

// ---------------- helpers (fragment maps verified in R9) ----------------
__device__ __forceinline__ u32 smem_u32(const void* p) {
    u32 a;
    asm("{ .reg .u64 t; cvta.to.shared.u64 t, %1; cvt.u32.u64 %0, t; }" : "=r"(a) : "l"(p));
    return a;
}
__device__ __forceinline__ void ldsm4(u32* r, u32 addr) {
    asm volatile("ldmatrix.sync.aligned.m8n8.x4.shared.b16 {%0,%1,%2,%3}, [%4];"
                 : "=r"(r[0]), "=r"(r[1]), "=r"(r[2]), "=r"(r[3]) : "r"(addr));
}
__device__ __forceinline__ void mma_f16(float* c, const u32* a, const u32* b) {
    asm volatile("mma.sync.aligned.m16n8k16.row.col.f32.f16.f16.f32 "
                 "{%0,%1,%2,%3}, {%4,%5,%6,%7}, {%8,%9}, {%0,%1,%2,%3};"
                 : "+f"(c[0]), "+f"(c[1]), "+f"(c[2]), "+f"(c[3])
                 : "r"(a[0]), "r"(a[1]), "r"(a[2]), "r"(a[3]), "r"(b[0]), "r"(b[1]));
}
// Single-MUFU activations (sm_75+ tanh unit)
__device__ __forceinline__ float tanh_hw(float v) {
    float r; asm("tanh.approx.f32 %0, %1;" : "=f"(r) : "f"(v)); return r;
}
__device__ __forceinline__ float sigm(float v) {
    return fmaf(0.5f, tanh_hw(0.5f * v), 0.5f);
}

// A-fragment (m16k16) in an h tile (pitch HPB); kchunk 0-3 = hi cols, 4-7 = lo cols
__device__ __forceinline__ u32 a_addr(u32 tile, int m0, int kchunk, int lane) {
    int r  = m0 + (lane & 15);
    int cb = kchunk * 32 + ((lane >> 4) << 4);
    return tile + r * HPB + cb;
}
// B-fragment x4 (one n8 tile, two k16 tiles starting at kchunk)
__device__ __forceinline__ u32 b_addr(u32 sbB, int pitch, int nt, int kchunk, int lane) {
    int n  = nt * 8 + (lane & 7);
    int cb = kchunk * 32 + ((lane >> 3) << 4);
    return sbB + n * pitch + cb;
}

// Regroup D-frag gates (verified): lane ends owning (i,f,g,o) of ONE (row,unit)
__device__ __forceinline__ void regroup(const float* C, int lane,
                                        float& gi_, float& gf, float& gg, float& go) {
    float v  = (lane & 1) ? C[0] : C[2];
    float sv = __shfl_xor_sync(0xFFFFFFFFu, v, 1);
    float w  = (lane & 1) ? C[1] : C[3];
    float sw = __shfl_xor_sync(0xFFFFFFFFu, w, 1);
    if (lane & 1) { gi_ = sv;   gf = sw;   gg = C[2]; go = C[3]; }
    else          { gi_ = C[0]; gf = C[1]; gg = sv;   go = sw;  }
}

// fp16 hi/lo split store of h into an h tile
__device__ __forceinline__ void store_h_tile(char* smem, int tileoff, int row, int j, float h) {
    __half hh = __float2half_rn(h);
    __half hl = __float2half_rn(h - __half2float(hh));
    *(__half*)(smem + tileoff + row * HPB + j * 2)       = hh;
    *(__half*)(smem + tileoff + row * HPB + 128 + j * 2) = hl;
}

// Layer-1 epilogue: writes h1 into tile h1off (no barrier: other buffer)
__device__ __forceinline__ void epi_l1(
    float acc[2][5][4], int cnt, int nt0, int lane, int jpar, const int* rows,
    const float4* b1q, const float4* wxq, const float* xv,
    float c1[2][5], char* smem, int h1off)
{
    #pragma unroll
    for (int mt = 0; mt < 2; ++mt) {
        #pragma unroll
        for (int nti = 0; nti < 5; ++nti) if (nti < cnt) {
            float gi_, gf, gg, go;
            regroup(acc[mt][nti], lane, gi_, gf, gg, go);
            int j = 2 * (nt0 + nti) + jpar;
            float4 b  = b1q[j];
            float4 wx = wxq[j];
            float pi = fmaf(xv[mt], wx.x, gi_ + b.x);
            float pf = fmaf(xv[mt], wx.y, gf + b.y);
            float pg = fmaf(xv[mt], wx.z, gg + b.z);
            float po = fmaf(xv[mt], wx.w, go + b.w);
            float cn = fmaf(sigm(pf), c1[mt][nti], sigm(pi) * tanh_hw(pg));
            c1[mt][nti] = cn;
            float h = sigm(po) * tanh_hw(cn);
            if (j < NS) store_h_tile(smem, h1off, rows[mt], j, h);
        }
    }
}

// Layer-2 epilogue: writes h2 (in place) + y partials
__device__ __forceinline__ void epi_l2(
    float acc[2][5][4], int cnt, int nt0, int lane, int jpar, const int* rows,
    const float4* b2q, const float* wls,
    float c2[2][5], char* smem, float* yw, int ng)
{
    #pragma unroll
    for (int mt = 0; mt < 2; ++mt) {
        float yp = 0.0f;
        #pragma unroll
        for (int nti = 0; nti < 5; ++nti) if (nti < cnt) {
            float gi_, gf, gg, go;
            regroup(acc[mt][nti], lane, gi_, gf, gg, go);
            int j = 2 * (nt0 + nti) + jpar;
            float4 b = b2q[j];
            float pi = gi_ + b.x, pf = gf + b.y, pg = gg + b.z, po = go + b.w;
            float cn = fmaf(sigm(pf), c2[mt][nti], sigm(pi) * tanh_hw(pg));
            c2[mt][nti] = cn;
            float h = sigm(po) * tanh_hw(cn);
            if (j < NS) {
                store_h_tile(smem, OFF_H2, rows[mt], j, h);
                yp = fmaf(wls[j], h, yp);
            }
        }
        float ys = yp + __shfl_xor_sync(0xFFFFFFFFu, yp, 2);
        if (!(lane & 2)) yw[rows[mt] * 8 + ng] = ys;
    }
}

__global__ __launch_bounds__(NTHREADS, 1)
void lstm2_hmma15_kernel(
    const float* __restrict__ x,      // [B, T]
    const float* __restrict__ Wih1,   // [204, 1]
    const float* __restrict__ Whh1,   // [204, 51]
    const float* __restrict__ bih1,
    const float* __restrict__ bhh1,
    const float* __restrict__ Wih2,   // [204, 51]
    const float* __restrict__ Whh2,   // [204, 51]
    const float* __restrict__ bih2,
    const float* __restrict__ bhh2,
    const float* __restrict__ Wlin,   // [1, 51]
    const float* __restrict__ blin,
    float* __restrict__ out)          // [B, T]
{
    extern __shared__ char smem[];
    const u32 sb = smem_u32(smem);
    const int tid  = threadIdx.x;
    const int wid  = tid >> 5;
    const int lane = tid & 31;
    const int mg   = wid / 6;                 // m-group 0/1 (rows 0-31 / 32-63)
    const int ng   = wid % 6;                 // n-group
    const int cnt  = (ng < 2) ? 5 : 4;
    const int nt0  = (ng < 2) ? 5 * ng : 10 + 4 * (ng - 2);
    const int rb   = blockIdx.x * M_ROWS;
    const int gtid = tid - 192 * mg;          // tid within my m-group
    const int barid = mg + 1;

    for (int i = tid; i < SMEM_TOTAL / 4; i += NTHREADS) ((u32*)smem)[i] = 0;
    __syncthreads();

    float4* b1q = (float4*)(smem + OFF_B1Q);
    float4* b2q = (float4*)(smem + OFF_B2Q);
    float4* wxq = (float4*)(smem + OFF_WXQ);
    float*  wls = (float*)(smem + OFF_WLS);
    float*  yw  = (float*)(smem + OFF_YW);

    // ---- stage weights: B row n = 4*j + gi, plain fp16 ----
    for (int idx = tid; idx < 208 * NS; idx += NTHREADS) {
        int n = idx / NS, m = idx % NS;
        int j = n >> 2, gi = n & 3;
        if (j < NS) {
            int g = gi * NS + j;
            *(__half*)(smem + OFF_B1 + n * B1P + m * 2)         = __float2half_rn(Whh1[g * NS + m]);
            *(__half*)(smem + OFF_B2 + n * B2P + m * 2)         = __float2half_rn(Wih2[g * NS + m]);
            *(__half*)(smem + OFF_B2 + n * B2P + 128 + m * 2)   = __float2half_rn(Whh2[g * NS + m]);
        }
    }
    for (int j = tid; j < NS; j += NTHREADS) {
        b1q[j] = make_float4(bih1[j] + bhh1[j], bih1[j + NS] + bhh1[j + NS],
                             bih1[j + 2 * NS] + bhh1[j + 2 * NS], bih1[j + 3 * NS] + bhh1[j + 3 * NS]);
        b2q[j] = make_float4(bih2[j] + bhh2[j], bih2[j + NS] + bhh2[j + NS],
                             bih2[j + 2 * NS] + bhh2[j + 2 * NS], bih2[j + 3 * NS] + bhh2[j + 3 * NS]);
        wxq[j] = make_float4(Wih1[j], Wih1[j + NS], Wih1[j + 2 * NS], Wih1[j + 3 * NS]);
        wls[j] = Wlin[j];
    }
    __syncthreads();

    const float blin_v = blin[0];
    const int m0base = 32 * mg;
    const int rbase  = m0base + (lane >> 2) + 8 * (lane & 1);
    const int rows[2] = {rbase, rbase + 16};
    const int jpar = (lane >> 1) & 1;
    const u32 sbB1 = sb + OFF_B1;
    const u32 sbB2 = sb + OFF_B2;
    const u32 h2t  = sb + OFF_H2;

    float c1[2][5], c2[2][5];
    #pragma unroll
    for (int mt = 0; mt < 2; ++mt)
        #pragma unroll
        for (int i = 0; i < 5; ++i) { c1[mt][i] = 0.0f; c2[mt][i] = 0.0f; }

    // ---- prologue: h1(0) = L1(x(0), h=0, c=0) into tile H1_0 ----
    {
        float acc0[2][5][4];
        #pragma unroll
        for (int mt = 0; mt < 2; ++mt)
            #pragma unroll
            for (int i = 0; i < 5; ++i)
                #pragma unroll
                for (int q = 0; q < 4; ++q) acc0[mt][i][q] = 0.0f;
        float xv0[2];
        #pragma unroll
        for (int mt = 0; mt < 2; ++mt)
            xv0[mt] = __ldg(&x[(size_t)(rb + rows[mt]) * T_LEN]);
        epi_l1(acc0, cnt, nt0, lane, jpar, rows, b1q, wxq, xv0, c1, smem, OFF_H1_0);
    }
    __syncthreads();

    // ---- main loop: all inter-step deps are m-group-private -> group barriers ----
    for (int t = 0; t < T_LEN; ++t) {
        const u32 h1cur   = sb + ((t & 1) ? OFF_H1_1 : OFF_H1_0);
        const int h1nxtOf = (t & 1) ? OFF_H1_0 : OFF_H1_1;

        // y(t-1) store (group-local rows), overlapped with MMA phase
        if (gtid < 32 && t > 0) {
            int r = m0base + gtid;
            float acc = blin_v;
            #pragma unroll
            for (int g2 = 0; g2 < 6; ++g2) acc += yw[r * 8 + g2];
            out[(size_t)(rb + r) * T_LEN + (t - 1)] = acc;
        }

        float xv[2];
        #pragma unroll
        for (int mt = 0; mt < 2; ++mt)
            xv[mt] = (t + 1 < T_LEN)
                   ? __ldg(&x[(size_t)(rb + rows[mt]) * T_LEN + t + 1]) : 0.0f;

        // ================= Phase 1: acc1 = h1(t) * W1, then epi_l1 =================
        {
            float acc1[2][5][4];
            #pragma unroll
            for (int mt = 0; mt < 2; ++mt)
                #pragma unroll
                for (int i = 0; i < 5; ++i)
                    #pragma unroll
                    for (int q = 0; q < 4; ++q) acc1[mt][i][q] = 0.0f;

            #pragma unroll
            for (int half = 0; half < 2; ++half) {
                u32 ahi[2][2][4], alo[2][2][4];
                #pragma unroll
                for (int mt = 0; mt < 2; ++mt)
                    #pragma unroll
                    for (int kk = 0; kk < 2; ++kk) {
                        ldsm4(ahi[mt][kk], a_addr(h1cur, m0base + 16 * mt, 2 * half + kk, lane));
                        ldsm4(alo[mt][kk], a_addr(h1cur, m0base + 16 * mt, 4 + 2 * half + kk, lane));
                    }
                #pragma unroll
                for (int nti = 0; nti < 5; ++nti) if (nti < cnt) {
                    int nt = nt0 + nti;
                    u32 bh[4];
                    ldsm4(bh, b_addr(sbB1, B1P, nt, 2 * half, lane));
                    #pragma unroll
                    for (int mt = 0; mt < 2; ++mt)
                        #pragma unroll
                        for (int kk = 0; kk < 2; ++kk) {
                            mma_f16(acc1[mt][nti], ahi[mt][kk], bh + 2 * kk);
                            mma_f16(acc1[mt][nti], alo[mt][kk], bh + 2 * kk);
                        }
                }
            }
            epi_l1(acc1, cnt, nt0, lane, jpar, rows, b1q, wxq, xv, c1, smem, h1nxtOf);
        }   // acc1 dead — register pressure released

        // ================= Phase 2: acc2 = h1(t)*Wi2 + h2(t-1)*Wh2 =================
        {
            float acc2[2][5][4];
            #pragma unroll
            for (int mt = 0; mt < 2; ++mt)
                #pragma unroll
                for (int i = 0; i < 5; ++i)
                    #pragma unroll
                    for (int q = 0; q < 4; ++q) acc2[mt][i][q] = 0.0f;

            // P2: h1 * Wi2  (B2 kchunks 0-3)
            #pragma unroll
            for (int half = 0; half < 2; ++half) {
                u32 ahi[2][2][4], alo[2][2][4];
                #pragma unroll
                for (int mt = 0; mt < 2; ++mt)
                    #pragma unroll
                    for (int kk = 0; kk < 2; ++kk) {
                        ldsm4(ahi[mt][kk], a_addr(h1cur, m0base + 16 * mt, 2 * half + kk, lane));
                        ldsm4(alo[mt][kk], a_addr(h1cur, m0base + 16 * mt, 4 + 2 * half + kk, lane));
                    }
                #pragma unroll
                for (int nti = 0; nti < 5; ++nti) if (nti < cnt) {
                    int nt = nt0 + nti;
                    u32 bh[4];
                    ldsm4(bh, b_addr(sbB2, B2P, nt, 2 * half, lane));
                    #pragma unroll
                    for (int mt = 0; mt < 2; ++mt)
                        #pragma unroll
                        for (int kk = 0; kk < 2; ++kk) {
                            mma_f16(acc2[mt][nti], ahi[mt][kk], bh + 2 * kk);
                            mma_f16(acc2[mt][nti], alo[mt][kk], bh + 2 * kk);
                        }
                }
            }
            // P3: h2 * Wh2  (B2 kchunks 4-7)
            #pragma unroll
            for (int half = 0; half < 2; ++half) {
                u32 ahi[2][2][4], alo[2][2][4];
                #pragma unroll
                for (int mt = 0; mt < 2; ++mt)
                    #pragma unroll
                    for (int kk = 0; kk < 2; ++kk) {
                        ldsm4(ahi[mt][kk], a_addr(h2t, m0base + 16 * mt, 2 * half + kk, lane));
                        ldsm4(alo[mt][kk], a_addr(h2t, m0base + 16 * mt, 4 + 2 * half + kk, lane));
                    }
                #pragma unroll
                for (int nti = 0; nti < 5; ++nti) if (nti < cnt) {
                    int nt = nt0 + nti;
                    u32 bh[4];
                    ldsm4(bh, b_addr(sbB2, B2P, nt, 4 + 2 * half, lane));
                    #pragma unroll
                    for (int mt = 0; mt < 2; ++mt)
                        #pragma unroll
                        for (int kk = 0; kk < 2; ++kk) {
                            mma_f16(acc2[mt][nti], ahi[mt][kk], bh + 2 * kk);
                            mma_f16(acc2[mt][nti], alo[mt][kk], bh + 2 * kk);
                        }
                }
            }

            // group barrier: my group's h2 reads (and yw reads) complete
            asm volatile("bar.sync %0, 192;" :: "r"(barid) : "memory");

            epi_l2(acc2, cnt, nt0, lane, jpar, rows, b2q, wls, c2, smem, yw, ng);
        }

        // group barrier: my group's h1(t+1), h2(t), yw(t) writes visible
        asm volatile("bar.sync %0, 192;" :: "r"(barid) : "memory");
    }

    // ---- final projection: y(T-1), group-local rows ----
    if (gtid < 32) {
        int r = m0base + gtid;
        float acc = blin_v;
        #pragma unroll
        for (int g2 = 0; g2 < 6; ++g2) acc += yw[r * 8 + g2];
        out[(size_t)(rb + r) * T_LEN + (T_LEN - 1)] = acc;
    }
}

extern "C" void kernel_launch(void* const* d_in, const int* in_sizes, int n_in,
                              void* d_out, int out_size) {
    const float* x    = (const float*)d_in[0];
    const float* Wih1 = (const float*)d_in[1];
    const float* Whh1 = (const float*)d_in[2];
    const float* bih1 = (const float*)d_in[3];
    const float* bhh1 = (const float*)d_in[4];
    const float* Wih2 = (const float*)d_in[5];
    const float* Whh2 = (const float*)d_in[6];
    const float* bih2 = (const float*)d_in[7];
    const float* bhh2 = (const float*)d_in[8];
    const float* Wlin = (const float*)d_in[9];
    const float* blin = (const float*)d_in[10];
    float* out = (float*)d_out;

    cudaFuncSetAttribute(lstm2_hmma15_kernel,
                         cudaFuncAttributeMaxDynamicSharedMemorySize, SMEM_TOTAL);

    dim3 grid(NCTA);          // 128 CTAs x 64 rows
    dim3 block(NTHREADS);     // 384 threads = 12 warps
    lstm2_hmma15_kernel<<<grid, block, SMEM_TOTAL>>>(
        x, Wih1, Whh1, bih1, bhh1, Wih2, Whh2, bih2, bhh2, Wlin, blin, out);
}